// round 7
// baseline (speedup 1.0000x reference)
#include <cuda_runtime.h>
#include <cuda_fp16.h>
#include <cstdint>

#define N_NODES 100000
#define DIMH 128
#define E_CAP 4000000
#define INS_STRIDE 130

// -------- scratch (device globals; no allocation allowed) --------
__device__ __align__(16) __half g_xh[(size_t)N_NODES * DIMH];   // fp16 copy of x
__device__ __align__(16) __half g_xwh[(size_t)N_NODES * DIMH];  // fp16 dinv-scaled xw
__device__ float g_dinv[N_NODES];
__device__ int   g_deg[N_NODES];   // zero at load; k_fill re-zeros each call
__device__ int   g_off[N_NODES + 1];
__device__ int   g_cur[N_NODES];
__device__ int   g_csr[E_CAP];
__device__ int2  g_edge[E_CAP];

// -------- packed f32x2 helpers --------
__device__ __forceinline__ unsigned long long pack2(float a, float b) {
    unsigned long long r;
    asm("mov.b64 %0, {%1,%2};" : "=l"(r) : "f"(a), "f"(b));
    return r;
}
__device__ __forceinline__ void ffma2(unsigned long long& d, unsigned long long a, unsigned long long b) {
    asm("fma.rn.f32x2 %0, %1, %2, %0;" : "+l"(d) : "l"(a), "l"(b));
}
__device__ __forceinline__ float2 unpack2(unsigned long long v) {
    float2 r;
    asm("mov.b64 {%0,%1}, %2;" : "=f"(r.x), "=f"(r.y) : "l"(v));
    return r;
}

// -------- count + edge conversion + x->fp16 --------
__global__ __launch_bounds__(256) void k_count(const void* __restrict__ ei,
                                               const float* __restrict__ x, int E) {
    __shared__ int s_is64;
    if (threadIdx.x < 32) {
        unsigned w = __ldg((const unsigned*)ei + threadIdx.x * 2 + 1);
        unsigned b = __ballot_sync(0xffffffffu, w != 0u);
        if (threadIdx.x == 0) s_is64 = (b == 0u);
    }
    __syncthreads();
    int gid = blockIdx.x * 256 + threadIdx.x;
    int total = gridDim.x * 256;
    if (gid < E) {
        int s, d;
        if (s_is64) {
            s = (int)__ldg((const long long*)ei + gid);
            d = (int)__ldg((const long long*)ei + E + gid);
        } else {
            s = __ldg((const int*)ei + gid);
            d = __ldg((const int*)ei + E + gid);
        }
        g_edge[gid] = make_int2(s, d);
        atomicAdd(&g_deg[d], 1);
    }
    const float2* x2 = (const float2*)x;
    __half2* xh2 = (__half2*)g_xh;
    const int NH2 = N_NODES * (DIMH / 2);
    for (int i = gid; i < NH2; i += total) {
        float2 v = __ldg(x2 + i);
        xh2[i] = __floats2half2_rn(v.x, v.y);
    }
}

// -------- coalesced tiled single-block scan (+ dinv) --------
__global__ __launch_bounds__(1024) void k_scan() {
    __shared__ int wsum[32];
    __shared__ int s_carry;
    int tid = threadIdx.x, lane = tid & 31, wid = tid >> 5;
    if (tid == 0) s_carry = 0;
    __syncthreads();
    const int NT = (N_NODES + 1023) / 1024;  // 98
    for (int t = 0; t < NT; t++) {
        int idx = t * 1024 + tid;
        int dg = (idx < N_NODES) ? g_deg[idx] : 0;
        int v = dg;
#pragma unroll
        for (int o = 1; o < 32; o <<= 1) {
            int u = __shfl_up_sync(~0u, v, o);
            if (lane >= o) v += u;
        }
        if (lane == 31) wsum[wid] = v;
        __syncthreads();
        if (wid == 0) {
            int w = wsum[lane];
#pragma unroll
            for (int o = 1; o < 32; o <<= 1) {
                int u = __shfl_up_sync(~0u, w, o);
                if (lane >= o) w += u;
            }
            wsum[lane] = w;
        }
        __syncthreads();
        int excl = v - dg + ((wid > 0) ? wsum[wid - 1] : 0) + s_carry;
        if (idx < N_NODES) {
            g_off[idx] = excl;
            g_cur[idx] = excl;
            g_dinv[idx] = rsqrtf((float)dg + 1.0f);
        }
        __syncthreads();
        if (tid == 0) s_carry += wsum[31];
        __syncthreads();
    }
    if (tid == 0) g_off[N_NODES] = s_carry;
}

// -------- fill CSR; re-zero g_deg for next call --------
__global__ __launch_bounds__(256) void k_fill(int E) {
    int e = blockIdx.x * 256 + threadIdx.x;
    int total = gridDim.x * 256;
    if (e < E) {
        int2 sd = g_edge[e];
        int pos = atomicAdd(&g_cur[sd.y], 1);
        g_csr[pos] = sd.x;
    }
    for (int i = e; i < N_NODES; i += total) g_deg[i] = 0;
}

// ===================== fused GIN-gather + 3-layer GEMM =====================
// block: 256 threads, 64 nodes. smem: Ws[128x128] (reloaded per phase),
// ins[64][130] (gather buf -> h1 -> h2), params[512].

__device__ __forceinline__ void load_W_swz(const float* __restrict__ W, float* __restrict__ Ws, int tid) {
    for (int i = tid; i < 4096; i += 256) {
        float4 v = __ldg((const float4*)W + i);
        int k = i >> 5, c4 = i & 31;
        ((float4*)Ws)[k * 32 + ((c4 & 3) * 8 + (c4 >> 2))] = v;
    }
}

__device__ __forceinline__ void gemm_core(const float* __restrict__ ins,
                                          const float* __restrict__ Ws,
                                          int tc, int tr, unsigned long long acc[16]) {
#pragma unroll
    for (int q = 0; q < 16; q++) acc[q] = 0ULL;
    const float* arow = ins + (tr * 2) * INS_STRIDE;
#pragma unroll 2
    for (int k = 0; k < 128; k += 2) {
        float2 a0 = *(const float2*)(arow + k);
        float2 a1 = *(const float2*)(arow + INS_STRIDE + k);
        unsigned long long a00 = pack2(a0.x, a0.x), a01 = pack2(a0.y, a0.y);
        unsigned long long a10 = pack2(a1.x, a1.x), a11 = pack2(a1.y, a1.y);
        const float* wk0 = Ws + k * 128 + tc * 4;
        const float* wk1 = wk0 + 128;
#pragma unroll
        for (int j = 0; j < 4; j++) {
            ulonglong2 w0 = *(const ulonglong2*)(wk0 + j * 32);
            ulonglong2 w1 = *(const ulonglong2*)(wk1 + j * 32);
            ffma2(acc[j * 2], a00, w0.x);     ffma2(acc[j * 2 + 1], a00, w0.y);
            ffma2(acc[8 + j * 2], a10, w0.x); ffma2(acc[8 + j * 2 + 1], a10, w0.y);
            ffma2(acc[j * 2], a01, w1.x);     ffma2(acc[j * 2 + 1], a01, w1.y);
            ffma2(acc[8 + j * 2], a11, w1.x); ffma2(acc[8 + j * 2 + 1], a11, w1.y);
        }
    }
}

__global__ __launch_bounds__(256) void k_mlp_fused(const float* __restrict__ x,
                                                   const float* __restrict__ W1,
                                                   const float* __restrict__ b1,
                                                   const float* __restrict__ gamma,
                                                   const float* __restrict__ beta,
                                                   const float* __restrict__ rmean,
                                                   const float* __restrict__ rvar,
                                                   const float* __restrict__ W2,
                                                   const float* __restrict__ b2,
                                                   const float* __restrict__ Wmu,
                                                   const float* __restrict__ bmu,
                                                   const float* __restrict__ Wls,
                                                   const float* __restrict__ bls,
                                                   float* __restrict__ out) {
    extern __shared__ float sm[];
    float* Ws = sm;                           // 16384
    float* ins = Ws + 16384;                  // 64*130 = 8320
    float* scale_s = ins + 64 * INS_STRIDE;   // 128
    float* shift_s = scale_s + 128;           // 128
    float* b2s = shift_s + 128;               // 128
    float* bcs = b2s + 128;                   // 128
    int tid = threadIdx.x;
    int wid = tid >> 5, lane = tid & 31;
    int node0 = blockIdx.x << 6;

    // ---- phase 0: params + W1 + GIN gather into ins ----
    if (tid < 128) {
        float sc = gamma[tid] * rsqrtf(rvar[tid] + 1e-5f);
        scale_s[tid] = sc;
        shift_s[tid] = (b1[tid] - rmean[tid]) * sc + beta[tid];
        b2s[tid] = b2[tid];
        bcs[tid] = (tid < 64) ? bmu[tid] : bls[tid - 64];
    }
    load_W_swz(W1, Ws, tid);

    const uint2* xh = (const uint2*)g_xh;
#pragma unroll 1
    for (int i = 0; i < 8; i++) {
        int nl = wid * 8 + i;
        int n = node0 + nl;
        int nn = (n < N_NODES) ? n : (N_NODES - 1);
        int beg = __ldg(g_off + nn), end = __ldg(g_off + nn + 1);
        float4 a0 = __ldg((const float4*)x + (size_t)nn * 32 + lane);
        float2 accA = make_float2(a0.x, a0.y);
        float2 accB = make_float2(a0.z, a0.w);
        int j = beg;
        for (; j + 8 <= end; j += 8) {
            int idx[8];
#pragma unroll
            for (int t = 0; t < 8; t++) idx[t] = __ldg(g_csr + j + t);
            uint2 v[8];
#pragma unroll
            for (int t = 0; t < 8; t++) v[t] = __ldg(xh + (size_t)idx[t] * 32 + lane);
#pragma unroll
            for (int t = 0; t < 8; t++) {
                float2 f0 = __half22float2(*(__half2*)&v[t].x);
                float2 f1 = __half22float2(*(__half2*)&v[t].y);
                accA.x += f0.x; accA.y += f0.y;
                accB.x += f1.x; accB.y += f1.y;
            }
        }
        for (; j < end; j++) {
            int s = __ldg(g_csr + j);
            uint2 v = __ldg(xh + (size_t)s * 32 + lane);
            float2 f0 = __half22float2(*(__half2*)&v.x);
            float2 f1 = __half22float2(*(__half2*)&v.y);
            accA.x += f0.x; accA.y += f0.y;
            accB.x += f1.x; accB.y += f1.y;
        }
        float* p = ins + nl * INS_STRIDE + lane * 4;
        ((float2*)p)[0] = accA;
        ((float2*)p)[1] = accB;
    }
    __syncthreads();

    int tc = tid & 7, tr = tid >> 3;
    unsigned long long acc[16];

    // ---- phase 1: h1 = relu(BN(ins @ W1)) ----
    gemm_core(ins, Ws, tc, tr, acc);
    __syncthreads();  // all reads of ins/Ws done
    {
        float* r0 = ins + (tr * 2) * INS_STRIDE;
        float* r1 = r0 + INS_STRIDE;
#pragma unroll
        for (int j = 0; j < 4; j++) {
            int c0 = tc * 16 + j * 4;
            float2 f0 = unpack2(acc[j * 2]),     f1 = unpack2(acc[j * 2 + 1]);
            float2 g0 = unpack2(acc[8 + j * 2]), g1 = unpack2(acc[8 + j * 2 + 1]);
            ((float2*)(r0 + c0))[0] = make_float2(
                fmaxf(f0.x * scale_s[c0 + 0] + shift_s[c0 + 0], 0.f),
                fmaxf(f0.y * scale_s[c0 + 1] + shift_s[c0 + 1], 0.f));
            ((float2*)(r0 + c0))[1] = make_float2(
                fmaxf(f1.x * scale_s[c0 + 2] + shift_s[c0 + 2], 0.f),
                fmaxf(f1.y * scale_s[c0 + 3] + shift_s[c0 + 3], 0.f));
            ((float2*)(r1 + c0))[0] = make_float2(
                fmaxf(g0.x * scale_s[c0 + 0] + shift_s[c0 + 0], 0.f),
                fmaxf(g0.y * scale_s[c0 + 1] + shift_s[c0 + 1], 0.f));
            ((float2*)(r1 + c0))[1] = make_float2(
                fmaxf(g1.x * scale_s[c0 + 2] + shift_s[c0 + 2], 0.f),
                fmaxf(g1.y * scale_s[c0 + 3] + shift_s[c0 + 3], 0.f));
        }
    }
    load_W_swz(W2, Ws, tid);
    __syncthreads();

    // ---- phase 2: h2 = relu(ins @ W2 + b2) ----
    gemm_core(ins, Ws, tc, tr, acc);
    __syncthreads();
    {
        float* r0 = ins + (tr * 2) * INS_STRIDE;
        float* r1 = r0 + INS_STRIDE;
#pragma unroll
        for (int j = 0; j < 4; j++) {
            int c0 = tc * 16 + j * 4;
            float2 f0 = unpack2(acc[j * 2]),     f1 = unpack2(acc[j * 2 + 1]);
            float2 g0 = unpack2(acc[8 + j * 2]), g1 = unpack2(acc[8 + j * 2 + 1]);
            ((float2*)(r0 + c0))[0] = make_float2(fmaxf(f0.x + b2s[c0 + 0], 0.f),
                                                  fmaxf(f0.y + b2s[c0 + 1], 0.f));
            ((float2*)(r0 + c0))[1] = make_float2(fmaxf(f1.x + b2s[c0 + 2], 0.f),
                                                  fmaxf(f1.y + b2s[c0 + 3], 0.f));
            ((float2*)(r1 + c0))[0] = make_float2(fmaxf(g0.x + b2s[c0 + 0], 0.f),
                                                  fmaxf(g0.y + b2s[c0 + 1], 0.f));
            ((float2*)(r1 + c0))[1] = make_float2(fmaxf(g1.x + b2s[c0 + 2], 0.f),
                                                  fmaxf(g1.y + b2s[c0 + 3], 0.f));
        }
    }
    // load concatenated [Wmu|Wls] swizzled
    for (int i = tid; i < 4096; i += 256) {
        int k = i >> 5, c4 = i & 31;
        float4 v = (c4 < 16) ? __ldg((const float4*)Wmu + k * 16 + c4)
                             : __ldg((const float4*)Wls + k * 16 + (c4 - 16));
        ((float4*)Ws)[k * 32 + ((c4 & 3) * 8 + (c4 >> 2))] = v;
    }
    __syncthreads();

    // ---- phase 3: xw = ins @ [Wmu|Wls]; xwh = half(dinv*xw); out = dinv^2*xw + b
    gemm_core(ins, Ws, tc, tr, acc);
#pragma unroll
    for (int i = 0; i < 2; i++) {
        int node = node0 + tr * 2 + i;
        if (node >= N_NODES) break;
        float dn = g_dinv[node];
#pragma unroll
        for (int j = 0; j < 4; j++) {
            int c0 = tc * 16 + j * 4;
            float2 f0 = unpack2(acc[i * 8 + j * 2]);
            float2 f1 = unpack2(acc[i * 8 + j * 2 + 1]);
            float4 xs = make_float4(dn * f0.x, dn * f0.y, dn * f1.x, dn * f1.y);
            uint2 hx;
            *(__half2*)&hx.x = __floats2half2_rn(xs.x, xs.y);
            *(__half2*)&hx.y = __floats2half2_rn(xs.z, xs.w);
            *(uint2*)(g_xwh + (size_t)node * 128 + c0) = hx;
            float4 ov;
            ov.x = dn * xs.x + bcs[c0 + 0];
            ov.y = dn * xs.y + bcs[c0 + 1];
            ov.z = dn * xs.z + bcs[c0 + 2];
            ov.w = dn * xs.w + bcs[c0 + 3];
            float* ob = (c0 < 64) ? (out + (size_t)node * 64 + c0)
                                  : (out + (size_t)N_NODES * 64 + (size_t)node * 64 + (c0 - 64));
            *(float4*)ob = ov;
        }
    }
}

// -------- GCN gather (fp16 rows): out[n] += dinv[n] * sum xwh[csr] ---------
__global__ __launch_bounds__(256) void k_gcn_gather(float* __restrict__ out) {
    int n = blockIdx.x * 8 + (threadIdx.x >> 5);
    if (n >= N_NODES) return;
    int lane = threadIdx.x & 31;
    int beg = __ldg(g_off + n), end = __ldg(g_off + n + 1);
    const uint2* xh = (const uint2*)g_xwh;
    float2 accA = make_float2(0.f, 0.f), accB = make_float2(0.f, 0.f);
    int j = beg;
    for (; j + 8 <= end; j += 8) {
        int idx[8];
#pragma unroll
        for (int t = 0; t < 8; t++) idx[t] = __ldg(g_csr + j + t);
        uint2 v[8];
#pragma unroll
        for (int t = 0; t < 8; t++) v[t] = __ldg(xh + (size_t)idx[t] * 32 + lane);
#pragma unroll
        for (int t = 0; t < 8; t++) {
            float2 f0 = __half22float2(*(__half2*)&v[t].x);
            float2 f1 = __half22float2(*(__half2*)&v[t].y);
            accA.x += f0.x; accA.y += f0.y;
            accB.x += f1.x; accB.y += f1.y;
        }
    }
    for (; j < end; j++) {
        int s = __ldg(g_csr + j);
        uint2 v = __ldg(xh + (size_t)s * 32 + lane);
        float2 f0 = __half22float2(*(__half2*)&v.x);
        float2 f1 = __half22float2(*(__half2*)&v.y);
        accA.x += f0.x; accA.y += f0.y;
        accB.x += f1.x; accB.y += f1.y;
    }
    float dn = g_dinv[n];
    int c0 = lane * 4;
    float* ob = (c0 < 64) ? (out + (size_t)n * 64 + c0)
                          : (out + (size_t)N_NODES * 64 + (size_t)n * 64 + (c0 - 64));
    float4 cur = *(float4*)ob;
    cur.x += dn * accA.x; cur.y += dn * accA.y;
    cur.z += dn * accB.x; cur.w += dn * accB.y;
    *(float4*)ob = cur;
}

extern "C" void kernel_launch(void* const* d_in, const int* in_sizes, int n_in,
                              void* d_out, int out_size) {
    const float* x     = (const float*)d_in[0];
    const void*  ei    = (const void*)d_in[1];
    const float* W1    = (const float*)d_in[2];
    const float* b1    = (const float*)d_in[3];
    const float* gamma = (const float*)d_in[4];
    const float* beta  = (const float*)d_in[5];
    const float* rmean = (const float*)d_in[6];
    const float* rvar  = (const float*)d_in[7];
    const float* W2    = (const float*)d_in[8];
    const float* b2    = (const float*)d_in[9];
    const float* Wmu   = (const float*)d_in[10];
    const float* bmu   = (const float*)d_in[11];
    const float* Wls   = (const float*)d_in[12];
    const float* bls   = (const float*)d_in[13];
    float* out = (float*)d_out;

    int E = in_sizes[1] / 2;

    const int SMEM = (16384 + 64 * INS_STRIDE + 512) * 4;  // 100864 B
    cudaFuncSetAttribute(k_mlp_fused, cudaFuncAttributeMaxDynamicSharedMemorySize, SMEM);

    int eb = (E + 255) / 256;
    int nb = (N_NODES + 7) / 8;
    int mb = (N_NODES + 63) / 64;

    k_count<<<eb, 256>>>(ei, x, E);                                    // 0
    k_scan<<<1, 1024>>>();                                             // 1
    k_fill<<<eb, 256>>>(E);                                            // 2
    k_mlp_fused<<<mb, 256, SMEM>>>(x, W1, b1, gamma, beta, rmean,      // 3 <- profiled
                                   rvar, W2, b2, Wmu, bmu, Wls, bls, out);
    k_gcn_gather<<<nb, 256>>>(out);                                    // 4
}

// round 8
// speedup vs baseline: 2.9149x; 2.9149x over previous
#include <cuda_runtime.h>
#include <cuda_fp16.h>
#include <cstdint>

#define N_NODES 100000
#define DIMH 128
#define E_CAP 4000000
#define WS_HALFS (128 * 136)
#define AS_HALFS (64 * 136)

// -------- scratch (device globals; no allocation allowed) --------
__device__ __align__(16) __half g_xh[(size_t)N_NODES * DIMH];   // fp16 copy of x
__device__ __align__(16) __half g_xwh[(size_t)N_NODES * DIMH];  // fp16 dinv-scaled xw
__device__ float g_dinv[N_NODES];
__device__ int   g_deg[N_NODES];   // zero at load; k_fill re-zeros each call
__device__ int   g_off[N_NODES + 1];
__device__ int   g_cur[N_NODES];
__device__ int   g_csr[E_CAP];
__device__ int2  g_edge[E_CAP];

// -------- count + edge conversion + x->fp16 --------
__global__ __launch_bounds__(256) void k_count(const void* __restrict__ ei,
                                               const float* __restrict__ x, int E) {
    __shared__ int s_is64;
    if (threadIdx.x < 32) {
        unsigned w = __ldg((const unsigned*)ei + threadIdx.x * 2 + 1);
        unsigned b = __ballot_sync(0xffffffffu, w != 0u);
        if (threadIdx.x == 0) s_is64 = (b == 0u);
    }
    __syncthreads();
    int gid = blockIdx.x * 256 + threadIdx.x;
    int total = gridDim.x * 256;
    if (gid < E) {
        int s, d;
        if (s_is64) {
            s = (int)__ldg((const long long*)ei + gid);
            d = (int)__ldg((const long long*)ei + E + gid);
        } else {
            s = __ldg((const int*)ei + gid);
            d = __ldg((const int*)ei + E + gid);
        }
        g_edge[gid] = make_int2(s, d);
        atomicAdd(&g_deg[d], 1);
    }
    const float2* x2 = (const float2*)x;
    __half2* xh2 = (__half2*)g_xh;
    const int NH2 = N_NODES * (DIMH / 2);
    for (int i = gid; i < NH2; i += total) {
        float2 v = __ldg(x2 + i);
        xh2[i] = __floats2half2_rn(v.x, v.y);
    }
}

// -------- coalesced tiled single-block scan (+ dinv) --------
__global__ __launch_bounds__(1024) void k_scan() {
    __shared__ int wsum[32];
    __shared__ int s_carry;
    int tid = threadIdx.x, lane = tid & 31, wid = tid >> 5;
    if (tid == 0) s_carry = 0;
    __syncthreads();
    const int NT = (N_NODES + 1023) / 1024;
    for (int t = 0; t < NT; t++) {
        int idx = t * 1024 + tid;
        int dg = (idx < N_NODES) ? g_deg[idx] : 0;
        int v = dg;
#pragma unroll
        for (int o = 1; o < 32; o <<= 1) {
            int u = __shfl_up_sync(~0u, v, o);
            if (lane >= o) v += u;
        }
        if (lane == 31) wsum[wid] = v;
        __syncthreads();
        if (wid == 0) {
            int w = wsum[lane];
#pragma unroll
            for (int o = 1; o < 32; o <<= 1) {
                int u = __shfl_up_sync(~0u, w, o);
                if (lane >= o) w += u;
            }
            wsum[lane] = w;
        }
        __syncthreads();
        int excl = v - dg + ((wid > 0) ? wsum[wid - 1] : 0) + s_carry;
        if (idx < N_NODES) {
            g_off[idx] = excl;
            g_cur[idx] = excl;
            g_dinv[idx] = rsqrtf((float)dg + 1.0f);
        }
        __syncthreads();
        if (tid == 0) s_carry += wsum[31];
        __syncthreads();
    }
    if (tid == 0) g_off[N_NODES] = s_carry;
}

// -------- fill CSR; re-zero g_deg for next call --------
__global__ __launch_bounds__(256) void k_fill(int E) {
    int e = blockIdx.x * 256 + threadIdx.x;
    int total = gridDim.x * 256;
    if (e < E) {
        int2 sd = g_edge[e];
        int pos = atomicAdd(&g_cur[sd.y], 1);
        g_csr[pos] = sd.x;
    }
    for (int i = e; i < N_NODES; i += total) g_deg[i] = 0;
}

// ===================== HMMA plumbing =====================
__device__ __forceinline__ uint32_t smem_u32(const void* p) {
    return (uint32_t)__cvta_generic_to_shared(p);
}
__device__ __forceinline__ void ldmat_x4(uint32_t addr, uint32_t& r0, uint32_t& r1,
                                         uint32_t& r2, uint32_t& r3) {
    asm volatile("ldmatrix.sync.aligned.m8n8.x4.shared.b16 {%0,%1,%2,%3}, [%4];"
                 : "=r"(r0), "=r"(r1), "=r"(r2), "=r"(r3) : "r"(addr));
}
__device__ __forceinline__ void ldmat_x4_t(uint32_t addr, uint32_t& r0, uint32_t& r1,
                                           uint32_t& r2, uint32_t& r3) {
    asm volatile("ldmatrix.sync.aligned.m8n8.x4.trans.shared.b16 {%0,%1,%2,%3}, [%4];"
                 : "=r"(r0), "=r"(r1), "=r"(r2), "=r"(r3) : "r"(addr));
}
__device__ __forceinline__ void mma16816(float* c, uint32_t a0, uint32_t a1, uint32_t a2,
                                         uint32_t a3, uint32_t b0, uint32_t b1) {
    asm volatile(
        "mma.sync.aligned.m16n8k16.row.col.f32.f16.f16.f32 "
        "{%0,%1,%2,%3}, {%4,%5,%6,%7}, {%8,%9}, {%0,%1,%2,%3};"
        : "+f"(c[0]), "+f"(c[1]), "+f"(c[2]), "+f"(c[3])
        : "r"(a0), "r"(a1), "r"(a2), "r"(a3), "r"(b0), "r"(b1));
}

// one GEMM phase: C[8][4] += As[wm*16.., :] @ Ws[:, wn*64..]
__device__ __forceinline__ void mma_phase(const __half* As, const __half* Ws,
                                          int wm, int wn, int lane, float C[8][4]) {
#pragma unroll
    for (int t = 0; t < 8; t++) {
        C[t][0] = 0.f; C[t][1] = 0.f; C[t][2] = 0.f; C[t][3] = 0.f;
    }
    int l15 = lane & 15, l16 = lane >> 4;
    const __half* abase = As + (wm * 16 + l15) * 136 + l16 * 8;
    const __half* bbase = Ws + l15 * 136 + wn * 64 + l16 * 8;
#pragma unroll
    for (int k = 0; k < 8; k++) {
        uint32_t a0, a1, a2, a3;
        ldmat_x4(smem_u32(abase + k * 16), a0, a1, a2, a3);
#pragma unroll
        for (int t = 0; t < 4; t++) {
            uint32_t b0, b1, b2, b3;
            ldmat_x4_t(smem_u32(bbase + (k * 16) * 136 + t * 16), b0, b1, b2, b3);
            mma16816(C[2 * t], a0, a1, a2, a3, b0, b1);
            mma16816(C[2 * t + 1], a0, a1, a2, a3, b2, b3);
        }
    }
}

// W [128x128] fp32 -> fp16 smem (stride 136)
__device__ __forceinline__ void load_W_half(const float* __restrict__ W,
                                            __half* __restrict__ Ws, int tid) {
    for (int i = tid; i < 4096; i += 256) {
        float4 v = __ldg((const float4*)W + i);
        int k = i >> 5, c4 = i & 31;
        uint2 h;
        *(__half2*)&h.x = __floats2half2_rn(v.x, v.y);
        *(__half2*)&h.y = __floats2half2_rn(v.z, v.w);
        *(uint2*)(Ws + k * 136 + c4 * 4) = h;
    }
}

// ===================== fused GIN-gather + 3-layer HMMA GEMM =====================
__global__ __launch_bounds__(256) void k_mlp_fused(const float* __restrict__ x,
                                                   const float* __restrict__ W1,
                                                   const float* __restrict__ b1,
                                                   const float* __restrict__ gamma,
                                                   const float* __restrict__ beta,
                                                   const float* __restrict__ rmean,
                                                   const float* __restrict__ rvar,
                                                   const float* __restrict__ W2,
                                                   const float* __restrict__ b2,
                                                   const float* __restrict__ Wmu,
                                                   const float* __restrict__ bmu,
                                                   const float* __restrict__ Wls,
                                                   const float* __restrict__ bls,
                                                   float* __restrict__ out) {
    extern __shared__ char smraw[];
    __half* Ws = (__half*)smraw;                       // 34816 B
    __half* As = (__half*)(smraw + WS_HALFS * 2);      // 17408 B
    float* scale_s = (float*)(smraw + WS_HALFS * 2 + AS_HALFS * 2);
    float* shift_s = scale_s + 128;
    float* b2s = shift_s + 128;
    float* bcs = b2s + 128;

    int tid = threadIdx.x, lane = tid & 31, wid = tid >> 5;
    int node0 = blockIdx.x << 6;

    // ---- phase 0: params + W1 + GIN gather into As (fp16) ----
    if (tid < 128) {
        float sc = gamma[tid] * rsqrtf(rvar[tid] + 1e-5f);
        scale_s[tid] = sc;
        shift_s[tid] = (b1[tid] - rmean[tid]) * sc + beta[tid];
        b2s[tid] = b2[tid];
        bcs[tid] = (tid < 64) ? bmu[tid] : bls[tid - 64];
    }
    load_W_half(W1, Ws, tid);

    const uint2* xh = (const uint2*)g_xh;
#pragma unroll 1
    for (int i = 0; i < 8; i++) {
        int nl = wid * 8 + i;
        int n = node0 + nl;
        int nn = (n < N_NODES) ? n : (N_NODES - 1);
        int beg = __ldg(g_off + nn), end = __ldg(g_off + nn + 1);
        float4 a0 = __ldg((const float4*)x + (size_t)nn * 32 + lane);
        float2 accA = make_float2(a0.x, a0.y);
        float2 accB = make_float2(a0.z, a0.w);
        int j = beg;
        for (; j + 8 <= end; j += 8) {
            int idx[8];
#pragma unroll
            for (int t = 0; t < 8; t++) idx[t] = __ldg(g_csr + j + t);
            uint2 v[8];
#pragma unroll
            for (int t = 0; t < 8; t++) v[t] = __ldg(xh + (size_t)idx[t] * 32 + lane);
#pragma unroll
            for (int t = 0; t < 8; t++) {
                float2 f0 = __half22float2(*(__half2*)&v[t].x);
                float2 f1 = __half22float2(*(__half2*)&v[t].y);
                accA.x += f0.x; accA.y += f0.y;
                accB.x += f1.x; accB.y += f1.y;
            }
        }
        for (; j < end; j++) {
            int s = __ldg(g_csr + j);
            uint2 v = __ldg(xh + (size_t)s * 32 + lane);
            float2 f0 = __half22float2(*(__half2*)&v.x);
            float2 f1 = __half22float2(*(__half2*)&v.y);
            accA.x += f0.x; accA.y += f0.y;
            accB.x += f1.x; accB.y += f1.y;
        }
        uint2 hx;
        *(__half2*)&hx.x = __floats2half2_rn(accA.x, accA.y);
        *(__half2*)&hx.y = __floats2half2_rn(accB.x, accB.y);
        *(uint2*)(As + nl * 136 + lane * 4) = hx;
    }
    __syncthreads();

    int wm = wid & 3, wn = wid >> 2;
    int r0 = wm * 16 + (lane >> 2);
    float C[8][4];

    // ---- phase 1: h1 = relu(BN(A @ W1)) ----
    mma_phase(As, Ws, wm, wn, lane, C);
    __syncthreads();
#pragma unroll
    for (int t = 0; t < 8; t++) {
        int c0 = wn * 64 + t * 8 + (lane & 3) * 2;
        float sc0 = scale_s[c0], sc1 = scale_s[c0 + 1];
        float sh0 = shift_s[c0], sh1 = shift_s[c0 + 1];
        *(__half2*)(As + r0 * 136 + c0) = __floats2half2_rn(
            fmaxf(C[t][0] * sc0 + sh0, 0.f), fmaxf(C[t][1] * sc1 + sh1, 0.f));
        *(__half2*)(As + (r0 + 8) * 136 + c0) = __floats2half2_rn(
            fmaxf(C[t][2] * sc0 + sh0, 0.f), fmaxf(C[t][3] * sc1 + sh1, 0.f));
    }
    load_W_half(W2, Ws, tid);
    __syncthreads();

    // ---- phase 2: h2 = relu(A @ W2 + b2) ----
    mma_phase(As, Ws, wm, wn, lane, C);
    __syncthreads();
#pragma unroll
    for (int t = 0; t < 8; t++) {
        int c0 = wn * 64 + t * 8 + (lane & 3) * 2;
        float bb0 = b2s[c0], bb1 = b2s[c0 + 1];
        *(__half2*)(As + r0 * 136 + c0) = __floats2half2_rn(
            fmaxf(C[t][0] + bb0, 0.f), fmaxf(C[t][1] + bb1, 0.f));
        *(__half2*)(As + (r0 + 8) * 136 + c0) = __floats2half2_rn(
            fmaxf(C[t][2] + bb0, 0.f), fmaxf(C[t][3] + bb1, 0.f));
    }
    // load concatenated [Wmu|Wls] fp16
    for (int i = tid; i < 4096; i += 256) {
        int k = i >> 5, c4 = i & 31;
        float4 v = (c4 < 16) ? __ldg((const float4*)Wmu + k * 16 + c4)
                             : __ldg((const float4*)Wls + k * 16 + (c4 - 16));
        uint2 h;
        *(__half2*)&h.x = __floats2half2_rn(v.x, v.y);
        *(__half2*)&h.y = __floats2half2_rn(v.z, v.w);
        *(uint2*)(Ws + k * 136 + c4 * 4) = h;
    }
    __syncthreads();

    // ---- phase 3: xw = A @ [Wmu|Wls]; xwh = half(dinv*xw); out = dinv^2*xw + b
    mma_phase(As, Ws, wm, wn, lane, C);
    {
        int nodeA = node0 + r0;
        int nodeB = nodeA + 8;
        bool okA = nodeA < N_NODES, okB = nodeB < N_NODES;
        float dnA = okA ? g_dinv[nodeA] : 0.f;
        float dnB = okB ? g_dinv[nodeB] : 0.f;
#pragma unroll
        for (int t = 0; t < 8; t++) {
            int c0 = wn * 64 + t * 8 + (lane & 3) * 2;
            float bb0 = bcs[c0], bb1 = bcs[c0 + 1];
            if (okA) {
                float x0 = dnA * C[t][0], x1 = dnA * C[t][1];
                *(__half2*)(g_xwh + (size_t)nodeA * 128 + c0) = __floats2half2_rn(x0, x1);
                float* ob = (c0 < 64) ? (out + (size_t)nodeA * 64 + c0)
                                      : (out + (size_t)N_NODES * 64 + (size_t)nodeA * 64 + (c0 - 64));
                *(float2*)ob = make_float2(dnA * x0 + bb0, dnA * x1 + bb1);
            }
            if (okB) {
                float x0 = dnB * C[t][2], x1 = dnB * C[t][3];
                *(__half2*)(g_xwh + (size_t)nodeB * 128 + c0) = __floats2half2_rn(x0, x1);
                float* ob = (c0 < 64) ? (out + (size_t)nodeB * 64 + c0)
                                      : (out + (size_t)N_NODES * 64 + (size_t)nodeB * 64 + (c0 - 64));
                *(float2*)ob = make_float2(dnB * x0 + bb0, dnB * x1 + bb1);
            }
        }
    }
}

// -------- GCN gather (fp16 rows): out[n] += dinv[n] * sum xwh[csr] ---------
__global__ __launch_bounds__(256) void k_gcn_gather(float* __restrict__ out) {
    int n = blockIdx.x * 8 + (threadIdx.x >> 5);
    if (n >= N_NODES) return;
    int lane = threadIdx.x & 31;
    int beg = __ldg(g_off + n), end = __ldg(g_off + n + 1);
    const uint2* xh = (const uint2*)g_xwh;
    float2 accA = make_float2(0.f, 0.f), accB = make_float2(0.f, 0.f);
    int j = beg;
    for (; j + 8 <= end; j += 8) {
        int idx[8];
#pragma unroll
        for (int t = 0; t < 8; t++) idx[t] = __ldg(g_csr + j + t);
        uint2 v[8];
#pragma unroll
        for (int t = 0; t < 8; t++) v[t] = __ldg(xh + (size_t)idx[t] * 32 + lane);
#pragma unroll
        for (int t = 0; t < 8; t++) {
            float2 f0 = __half22float2(*(__half2*)&v[t].x);
            float2 f1 = __half22float2(*(__half2*)&v[t].y);
            accA.x += f0.x; accA.y += f0.y;
            accB.x += f1.x; accB.y += f1.y;
        }
    }
    for (; j < end; j++) {
        int s = __ldg(g_csr + j);
        uint2 v = __ldg(xh + (size_t)s * 32 + lane);
        float2 f0 = __half22float2(*(__half2*)&v.x);
        float2 f1 = __half22float2(*(__half2*)&v.y);
        accA.x += f0.x; accA.y += f0.y;
        accB.x += f1.x; accB.y += f1.y;
    }
    float dn = g_dinv[n];
    int c0 = lane * 4;
    float* ob = (c0 < 64) ? (out + (size_t)n * 64 + c0)
                          : (out + (size_t)N_NODES * 64 + (size_t)n * 64 + (c0 - 64));
    float4 cur = *(float4*)ob;
    cur.x += dn * accA.x; cur.y += dn * accA.y;
    cur.z += dn * accB.x; cur.w += dn * accB.y;
    *(float4*)ob = cur;
}

extern "C" void kernel_launch(void* const* d_in, const int* in_sizes, int n_in,
                              void* d_out, int out_size) {
    const float* x     = (const float*)d_in[0];
    const void*  ei    = (const void*)d_in[1];
    const float* W1    = (const float*)d_in[2];
    const float* b1    = (const float*)d_in[3];
    const float* gamma = (const float*)d_in[4];
    const float* beta  = (const float*)d_in[5];
    const float* rmean = (const float*)d_in[6];
    const float* rvar  = (const float*)d_in[7];
    const float* W2    = (const float*)d_in[8];
    const float* b2    = (const float*)d_in[9];
    const float* Wmu   = (const float*)d_in[10];
    const float* bmu   = (const float*)d_in[11];
    const float* Wls   = (const float*)d_in[12];
    const float* bls   = (const float*)d_in[13];
    float* out = (float*)d_out;

    int E = in_sizes[1] / 2;

    const int SMEM = WS_HALFS * 2 + AS_HALFS * 2 + 512 * 4;  // 54272 B
    cudaFuncSetAttribute(k_mlp_fused, cudaFuncAttributeMaxDynamicSharedMemorySize, SMEM);

    int eb = (E + 255) / 256;
    int nb = (N_NODES + 7) / 8;
    int mb = (N_NODES + 63) / 64;

    k_count<<<eb, 256>>>(ei, x, E);                                    // 0
    k_scan<<<1, 1024>>>();                                             // 1
    k_fill<<<eb, 256>>>(E);                                            // 2
    k_mlp_fused<<<mb, 256, SMEM>>>(x, W1, b1, gamma, beta, rmean,      // 3 <- profiled
                                   rvar, W2, b2, Wmu, bmu, Wls, bls, out);
    k_gcn_gather<<<nb, 256>>>(out);                                    // 4
}

// round 9
// speedup vs baseline: 3.1864x; 1.0931x over previous
#include <cuda_runtime.h>
#include <cuda_fp16.h>
#include <cstdint>

#define N_NODES 100000
#define DIMH 128
#define E_CAP 4000000
#define WS_HALFS (128 * 136)
#define AS_HALFS (64 * 136)

// -------- scratch (device globals; no allocation allowed) --------
__device__ __align__(16) __half g_xh[(size_t)N_NODES * DIMH];    // fp16 copy of x
__device__ __align__(16) __half g_aggrh[(size_t)N_NODES * DIMH]; // fp16 x+sum(neigh)
__device__ __align__(16) __half g_xwh[(size_t)N_NODES * DIMH];   // fp16 dinv-scaled xw
__device__ float g_dinv[N_NODES];
__device__ int   g_deg[N_NODES];   // zero at load; k_fill re-zeros each call
__device__ int   g_off[N_NODES + 1];
__device__ int   g_cur[N_NODES];
__device__ int   g_csr[E_CAP];
__device__ int2  g_edge[E_CAP];

// -------- count + edge conversion + x->fp16 --------
__global__ __launch_bounds__(256) void k_count(const void* __restrict__ ei,
                                               const float* __restrict__ x, int E) {
    __shared__ int s_is64;
    if (threadIdx.x < 32) {
        unsigned w = __ldg((const unsigned*)ei + threadIdx.x * 2 + 1);
        unsigned b = __ballot_sync(0xffffffffu, w != 0u);
        if (threadIdx.x == 0) s_is64 = (b == 0u);
    }
    __syncthreads();
    int gid = blockIdx.x * 256 + threadIdx.x;
    int total = gridDim.x * 256;
    if (gid < E) {
        int s, d;
        if (s_is64) {
            s = (int)__ldg((const long long*)ei + gid);
            d = (int)__ldg((const long long*)ei + E + gid);
        } else {
            s = __ldg((const int*)ei + gid);
            d = __ldg((const int*)ei + E + gid);
        }
        g_edge[gid] = make_int2(s, d);
        atomicAdd(&g_deg[d], 1);
    }
    const float2* x2 = (const float2*)x;
    __half2* xh2 = (__half2*)g_xh;
    const int NH2 = N_NODES * (DIMH / 2);
    for (int i = gid; i < NH2; i += total) {
        float2 v = __ldg(x2 + i);
        xh2[i] = __floats2half2_rn(v.x, v.y);
    }
}

// -------- coalesced tiled single-block scan (+ dinv) --------
__global__ __launch_bounds__(1024) void k_scan() {
    __shared__ int wsum[32];
    __shared__ int s_carry;
    int tid = threadIdx.x, lane = tid & 31, wid = tid >> 5;
    if (tid == 0) s_carry = 0;
    __syncthreads();
    const int NT = (N_NODES + 1023) / 1024;
    for (int t = 0; t < NT; t++) {
        int idx = t * 1024 + tid;
        int dg = (idx < N_NODES) ? g_deg[idx] : 0;
        int v = dg;
#pragma unroll
        for (int o = 1; o < 32; o <<= 1) {
            int u = __shfl_up_sync(~0u, v, o);
            if (lane >= o) v += u;
        }
        if (lane == 31) wsum[wid] = v;
        __syncthreads();
        if (wid == 0) {
            int w = wsum[lane];
#pragma unroll
            for (int o = 1; o < 32; o <<= 1) {
                int u = __shfl_up_sync(~0u, w, o);
                if (lane >= o) w += u;
            }
            wsum[lane] = w;
        }
        __syncthreads();
        int excl = v - dg + ((wid > 0) ? wsum[wid - 1] : 0) + s_carry;
        if (idx < N_NODES) {
            g_off[idx] = excl;
            g_cur[idx] = excl;
            g_dinv[idx] = rsqrtf((float)dg + 1.0f);
        }
        __syncthreads();
        if (tid == 0) s_carry += wsum[31];
        __syncthreads();
    }
    if (tid == 0) g_off[N_NODES] = s_carry;
}

// -------- fill CSR; re-zero g_deg for next call --------
__global__ __launch_bounds__(256) void k_fill(int E) {
    int e = blockIdx.x * 256 + threadIdx.x;
    int total = gridDim.x * 256;
    if (e < E) {
        int2 sd = g_edge[e];
        int pos = atomicAdd(&g_cur[sd.y], 1);
        g_csr[pos] = sd.x;
    }
    for (int i = e; i < N_NODES; i += total) g_deg[i] = 0;
}

// -------- GIN gather (fp16): aggrh[n] = half(x[n] + sum xh[csr]) -----------
__global__ __launch_bounds__(256) void k_gin_gather(const float* __restrict__ x) {
    int n = blockIdx.x * 8 + (threadIdx.x >> 5);
    if (n >= N_NODES) return;
    int lane = threadIdx.x & 31;
    int beg = __ldg(g_off + n), end = __ldg(g_off + n + 1);
    const uint2* xh = (const uint2*)g_xh;
    float4 a0 = __ldg((const float4*)x + (size_t)n * 32 + lane);
    float2 accA = make_float2(a0.x, a0.y);
    float2 accB = make_float2(a0.z, a0.w);
    int j = beg;
    for (; j + 8 <= end; j += 8) {
        int idx[8];
#pragma unroll
        for (int t = 0; t < 8; t++) idx[t] = __ldg(g_csr + j + t);
        uint2 v[8];
#pragma unroll
        for (int t = 0; t < 8; t++) v[t] = __ldg(xh + (size_t)idx[t] * 32 + lane);
#pragma unroll
        for (int t = 0; t < 8; t++) {
            float2 f0 = __half22float2(*(__half2*)&v[t].x);
            float2 f1 = __half22float2(*(__half2*)&v[t].y);
            accA.x += f0.x; accA.y += f0.y;
            accB.x += f1.x; accB.y += f1.y;
        }
    }
    for (; j < end; j++) {
        int s = __ldg(g_csr + j);
        uint2 v = __ldg(xh + (size_t)s * 32 + lane);
        float2 f0 = __half22float2(*(__half2*)&v.x);
        float2 f1 = __half22float2(*(__half2*)&v.y);
        accA.x += f0.x; accA.y += f0.y;
        accB.x += f1.x; accB.y += f1.y;
    }
    uint2 hx;
    *(__half2*)&hx.x = __floats2half2_rn(accA.x, accA.y);
    *(__half2*)&hx.y = __floats2half2_rn(accB.x, accB.y);
    *(uint2*)(g_aggrh + (size_t)n * 128 + lane * 4) = hx;
}

// ===================== HMMA plumbing =====================
__device__ __forceinline__ uint32_t smem_u32(const void* p) {
    return (uint32_t)__cvta_generic_to_shared(p);
}
__device__ __forceinline__ void ldmat_x4(uint32_t addr, uint32_t& r0, uint32_t& r1,
                                         uint32_t& r2, uint32_t& r3) {
    asm volatile("ldmatrix.sync.aligned.m8n8.x4.shared.b16 {%0,%1,%2,%3}, [%4];"
                 : "=r"(r0), "=r"(r1), "=r"(r2), "=r"(r3) : "r"(addr));
}
__device__ __forceinline__ void ldmat_x4_t(uint32_t addr, uint32_t& r0, uint32_t& r1,
                                           uint32_t& r2, uint32_t& r3) {
    asm volatile("ldmatrix.sync.aligned.m8n8.x4.trans.shared.b16 {%0,%1,%2,%3}, [%4];"
                 : "=r"(r0), "=r"(r1), "=r"(r2), "=r"(r3) : "r"(addr));
}
__device__ __forceinline__ void mma16816(float* c, uint32_t a0, uint32_t a1, uint32_t a2,
                                         uint32_t a3, uint32_t b0, uint32_t b1) {
    asm volatile(
        "mma.sync.aligned.m16n8k16.row.col.f32.f16.f16.f32 "
        "{%0,%1,%2,%3}, {%4,%5,%6,%7}, {%8,%9}, {%0,%1,%2,%3};"
        : "+f"(c[0]), "+f"(c[1]), "+f"(c[2]), "+f"(c[3])
        : "r"(a0), "r"(a1), "r"(a2), "r"(a3), "r"(b0), "r"(b1));
}

__device__ __forceinline__ void mma_phase(const __half* As, const __half* Ws,
                                          int wm, int wn, int lane, float C[8][4]) {
#pragma unroll
    for (int t = 0; t < 8; t++) {
        C[t][0] = 0.f; C[t][1] = 0.f; C[t][2] = 0.f; C[t][3] = 0.f;
    }
    int l15 = lane & 15, l16 = lane >> 4;
    const __half* abase = As + (wm * 16 + l15) * 136 + l16 * 8;
    const __half* bbase = Ws + l15 * 136 + wn * 64 + l16 * 8;
#pragma unroll
    for (int k = 0; k < 8; k++) {
        uint32_t a0, a1, a2, a3;
        ldmat_x4(smem_u32(abase + k * 16), a0, a1, a2, a3);
#pragma unroll
        for (int t = 0; t < 4; t++) {
            uint32_t b0, b1, b2, b3;
            ldmat_x4_t(smem_u32(bbase + (k * 16) * 136 + t * 16), b0, b1, b2, b3);
            mma16816(C[2 * t], a0, a1, a2, a3, b0, b1);
            mma16816(C[2 * t + 1], a0, a1, a2, a3, b2, b3);
        }
    }
}

__device__ __forceinline__ void load_W_half(const float* __restrict__ W,
                                            __half* __restrict__ Ws, int tid) {
    for (int i = tid; i < 4096; i += 256) {
        float4 v = __ldg((const float4*)W + i);
        int k = i >> 5, c4 = i & 31;
        uint2 h;
        *(__half2*)&h.x = __floats2half2_rn(v.x, v.y);
        *(__half2*)&h.y = __floats2half2_rn(v.z, v.w);
        *(uint2*)(Ws + k * 136 + c4 * 4) = h;
    }
}

// ===================== 3-layer HMMA GEMM (reads g_aggrh) =====================
__global__ __launch_bounds__(256) void k_mlp_hmma(const float* __restrict__ W1,
                                                  const float* __restrict__ b1,
                                                  const float* __restrict__ gamma,
                                                  const float* __restrict__ beta,
                                                  const float* __restrict__ rmean,
                                                  const float* __restrict__ rvar,
                                                  const float* __restrict__ W2,
                                                  const float* __restrict__ b2,
                                                  const float* __restrict__ Wmu,
                                                  const float* __restrict__ bmu,
                                                  const float* __restrict__ Wls,
                                                  const float* __restrict__ bls,
                                                  float* __restrict__ out) {
    extern __shared__ char smraw[];
    __half* Ws = (__half*)smraw;
    __half* As = (__half*)(smraw + WS_HALFS * 2);
    float* scale_s = (float*)(smraw + WS_HALFS * 2 + AS_HALFS * 2);
    float* shift_s = scale_s + 128;
    float* b2s = shift_s + 128;
    float* bcs = b2s + 128;

    int tid = threadIdx.x, lane = tid & 31, wid = tid >> 5;
    int node0 = blockIdx.x << 6;

    if (tid < 128) {
        float sc = gamma[tid] * rsqrtf(rvar[tid] + 1e-5f);
        scale_s[tid] = sc;
        shift_s[tid] = (b1[tid] - rmean[tid]) * sc + beta[tid];
        b2s[tid] = b2[tid];
        bcs[tid] = (tid < 64) ? bmu[tid] : bls[tid - 64];
    }
    load_W_half(W1, Ws, tid);
    // load 64 aggr rows (fp16) coalesced
    for (int i = tid; i < 2048; i += 256) {
        int n = i >> 5, q = i & 31;
        int node = node0 + n;
        if (node > N_NODES - 1) node = N_NODES - 1;
        uint2 h = __ldg((const uint2*)(g_aggrh + (size_t)node * 128) + q);
        *(uint2*)(As + n * 136 + q * 4) = h;
    }
    __syncthreads();

    int wm = wid & 3, wn = wid >> 2;
    int r0 = wm * 16 + (lane >> 2);
    float C[8][4];

    // ---- phase 1: h1 = relu(BN(A @ W1)) ----
    mma_phase(As, Ws, wm, wn, lane, C);
    __syncthreads();
#pragma unroll
    for (int t = 0; t < 8; t++) {
        int c0 = wn * 64 + t * 8 + (lane & 3) * 2;
        float sc0 = scale_s[c0], sc1 = scale_s[c0 + 1];
        float sh0 = shift_s[c0], sh1 = shift_s[c0 + 1];
        *(__half2*)(As + r0 * 136 + c0) = __floats2half2_rn(
            fmaxf(C[t][0] * sc0 + sh0, 0.f), fmaxf(C[t][1] * sc1 + sh1, 0.f));
        *(__half2*)(As + (r0 + 8) * 136 + c0) = __floats2half2_rn(
            fmaxf(C[t][2] * sc0 + sh0, 0.f), fmaxf(C[t][3] * sc1 + sh1, 0.f));
    }
    load_W_half(W2, Ws, tid);
    __syncthreads();

    // ---- phase 2: h2 = relu(A @ W2 + b2) ----
    mma_phase(As, Ws, wm, wn, lane, C);
    __syncthreads();
#pragma unroll
    for (int t = 0; t < 8; t++) {
        int c0 = wn * 64 + t * 8 + (lane & 3) * 2;
        float bb0 = b2s[c0], bb1 = b2s[c0 + 1];
        *(__half2*)(As + r0 * 136 + c0) = __floats2half2_rn(
            fmaxf(C[t][0] + bb0, 0.f), fmaxf(C[t][1] + bb1, 0.f));
        *(__half2*)(As + (r0 + 8) * 136 + c0) = __floats2half2_rn(
            fmaxf(C[t][2] + bb0, 0.f), fmaxf(C[t][3] + bb1, 0.f));
    }
    for (int i = tid; i < 4096; i += 256) {
        int k = i >> 5, c4 = i & 31;
        float4 v = (c4 < 16) ? __ldg((const float4*)Wmu + k * 16 + c4)
                             : __ldg((const float4*)Wls + k * 16 + (c4 - 16));
        uint2 h;
        *(__half2*)&h.x = __floats2half2_rn(v.x, v.y);
        *(__half2*)&h.y = __floats2half2_rn(v.z, v.w);
        *(uint2*)(Ws + k * 136 + c4 * 4) = h;
    }
    __syncthreads();

    // ---- phase 3: xw = A @ [Wmu|Wls]; xwh = half(dinv*xw); out = dinv^2*xw + b
    mma_phase(As, Ws, wm, wn, lane, C);
    {
        int nodeA = node0 + r0;
        int nodeB = nodeA + 8;
        bool okA = nodeA < N_NODES, okB = nodeB < N_NODES;
        float dnA = okA ? g_dinv[nodeA] : 0.f;
        float dnB = okB ? g_dinv[nodeB] : 0.f;
#pragma unroll
        for (int t = 0; t < 8; t++) {
            int c0 = wn * 64 + t * 8 + (lane & 3) * 2;
            float bb0 = bcs[c0], bb1 = bcs[c0 + 1];
            if (okA) {
                float x0 = dnA * C[t][0], x1 = dnA * C[t][1];
                *(__half2*)(g_xwh + (size_t)nodeA * 128 + c0) = __floats2half2_rn(x0, x1);
                float* ob = (c0 < 64) ? (out + (size_t)nodeA * 64 + c0)
                                      : (out + (size_t)N_NODES * 64 + (size_t)nodeA * 64 + (c0 - 64));
                *(float2*)ob = make_float2(dnA * x0 + bb0, dnA * x1 + bb1);
            }
            if (okB) {
                float x0 = dnB * C[t][2], x1 = dnB * C[t][3];
                *(__half2*)(g_xwh + (size_t)nodeB * 128 + c0) = __floats2half2_rn(x0, x1);
                float* ob = (c0 < 64) ? (out + (size_t)nodeB * 64 + c0)
                                      : (out + (size_t)N_NODES * 64 + (size_t)nodeB * 64 + (c0 - 64));
                *(float2*)ob = make_float2(dnB * x0 + bb0, dnB * x1 + bb1);
            }
        }
    }
}

// -------- GCN gather (fp16 rows): out[n] += dinv[n] * sum xwh[csr] ---------
__global__ __launch_bounds__(256) void k_gcn_gather(float* __restrict__ out) {
    int n = blockIdx.x * 8 + (threadIdx.x >> 5);
    if (n >= N_NODES) return;
    int lane = threadIdx.x & 31;
    int beg = __ldg(g_off + n), end = __ldg(g_off + n + 1);
    const uint2* xh = (const uint2*)g_xwh;
    float2 accA = make_float2(0.f, 0.f), accB = make_float2(0.f, 0.f);
    int j = beg;
    for (; j + 8 <= end; j += 8) {
        int idx[8];
#pragma unroll
        for (int t = 0; t < 8; t++) idx[t] = __ldg(g_csr + j + t);
        uint2 v[8];
#pragma unroll
        for (int t = 0; t < 8; t++) v[t] = __ldg(xh + (size_t)idx[t] * 32 + lane);
#pragma unroll
        for (int t = 0; t < 8; t++) {
            float2 f0 = __half22float2(*(__half2*)&v[t].x);
            float2 f1 = __half22float2(*(__half2*)&v[t].y);
            accA.x += f0.x; accA.y += f0.y;
            accB.x += f1.x; accB.y += f1.y;
        }
    }
    for (; j < end; j++) {
        int s = __ldg(g_csr + j);
        uint2 v = __ldg(xh + (size_t)s * 32 + lane);
        float2 f0 = __half22float2(*(__half2*)&v.x);
        float2 f1 = __half22float2(*(__half2*)&v.y);
        accA.x += f0.x; accA.y += f0.y;
        accB.x += f1.x; accB.y += f1.y;
    }
    float dn = g_dinv[n];
    int c0 = lane * 4;
    float* ob = (c0 < 64) ? (out + (size_t)n * 64 + c0)
                          : (out + (size_t)N_NODES * 64 + (size_t)n * 64 + (c0 - 64));
    float4 cur = *(float4*)ob;
    cur.x += dn * accA.x; cur.y += dn * accA.y;
    cur.z += dn * accB.x; cur.w += dn * accB.y;
    *(float4*)ob = cur;
}

extern "C" void kernel_launch(void* const* d_in, const int* in_sizes, int n_in,
                              void* d_out, int out_size) {
    const float* x     = (const float*)d_in[0];
    const void*  ei    = (const void*)d_in[1];
    const float* W1    = (const float*)d_in[2];
    const float* b1    = (const float*)d_in[3];
    const float* gamma = (const float*)d_in[4];
    const float* beta  = (const float*)d_in[5];
    const float* rmean = (const float*)d_in[6];
    const float* rvar  = (const float*)d_in[7];
    const float* W2    = (const float*)d_in[8];
    const float* b2    = (const float*)d_in[9];
    const float* Wmu   = (const float*)d_in[10];
    const float* bmu   = (const float*)d_in[11];
    const float* Wls   = (const float*)d_in[12];
    const float* bls   = (const float*)d_in[13];
    float* out = (float*)d_out;

    int E = in_sizes[1] / 2;

    const int SMEM = WS_HALFS * 2 + AS_HALFS * 2 + 512 * 4;  // 54272 B
    cudaFuncSetAttribute(k_mlp_hmma, cudaFuncAttributeMaxDynamicSharedMemorySize, SMEM);

    int eb = (E + 255) / 256;
    int nb = (N_NODES + 7) / 8;
    int mb = (N_NODES + 63) / 64;

    k_count<<<eb, 256>>>(ei, x, E);                                    // 0
    k_scan<<<1, 1024>>>();                                             // 1
    k_fill<<<eb, 256>>>(E);                                            // 2
    k_gin_gather<<<nb, 256>>>(x);                                      // 3 <- profiled
    k_mlp_hmma<<<mb, 256, SMEM>>>(W1, b1, gamma, beta, rmean, rvar,    // 4
                                  W2, b2, Wmu, bmu, Wls, bls, out);
    k_gcn_gather<<<nb, 256>>>(out);                                    // 5
}

// round 10
// speedup vs baseline: 3.4196x; 1.0732x over previous
#include <cuda_runtime.h>
#include <cuda_fp16.h>
#include <cstdint>

#define N_NODES 100000
#define DIMH 128
#define E_CAP 4000000
#define WS_HALFS (128 * 136)
#define AS_HALFS (128 * 136)

// -------- scratch (device globals; no allocation allowed) --------
__device__ __align__(16) __half g_xh[(size_t)N_NODES * DIMH];    // fp16 copy of x
__device__ __align__(16) __half g_aggrh[(size_t)N_NODES * DIMH]; // fp16 x+sum(neigh)
__device__ __align__(16) __half g_xwh[(size_t)N_NODES * DIMH];   // fp16 dinv-scaled xw
__device__ float g_dinv[N_NODES];
__device__ int   g_deg[N_NODES];   // zero at load; k_fill re-zeros each call
__device__ int   g_off[N_NODES + 1];
__device__ int   g_cur[N_NODES];
__device__ int   g_csr[E_CAP];
__device__ int2  g_edge[E_CAP];

// -------- count + edge conversion + x->fp16 --------
__global__ __launch_bounds__(256) void k_count(const void* __restrict__ ei,
                                               const float* __restrict__ x, int E) {
    __shared__ int s_is64;
    if (threadIdx.x < 32) {
        unsigned w = __ldg((const unsigned*)ei + threadIdx.x * 2 + 1);
        unsigned b = __ballot_sync(0xffffffffu, w != 0u);
        if (threadIdx.x == 0) s_is64 = (b == 0u);
    }
    __syncthreads();
    int gid = blockIdx.x * 256 + threadIdx.x;
    int total = gridDim.x * 256;
    if (gid < E) {
        int s, d;
        if (s_is64) {
            s = (int)__ldg((const long long*)ei + gid);
            d = (int)__ldg((const long long*)ei + E + gid);
        } else {
            s = __ldg((const int*)ei + gid);
            d = __ldg((const int*)ei + E + gid);
        }
        g_edge[gid] = make_int2(s, d);
        atomicAdd(&g_deg[d], 1);
    }
    const float2* x2 = (const float2*)x;
    __half2* xh2 = (__half2*)g_xh;
    const int NH2 = N_NODES * (DIMH / 2);
    for (int i = gid; i < NH2; i += total) {
        float2 v = __ldg(x2 + i);
        xh2[i] = __floats2half2_rn(v.x, v.y);
    }
}

// -------- coalesced tiled single-block scan (+ dinv) --------
__global__ __launch_bounds__(1024) void k_scan() {
    __shared__ int wsum[32];
    __shared__ int s_carry;
    int tid = threadIdx.x, lane = tid & 31, wid = tid >> 5;
    if (tid == 0) s_carry = 0;
    __syncthreads();
    const int NT = (N_NODES + 1023) / 1024;
    for (int t = 0; t < NT; t++) {
        int idx = t * 1024 + tid;
        int dg = (idx < N_NODES) ? g_deg[idx] : 0;
        int v = dg;
#pragma unroll
        for (int o = 1; o < 32; o <<= 1) {
            int u = __shfl_up_sync(~0u, v, o);
            if (lane >= o) v += u;
        }
        if (lane == 31) wsum[wid] = v;
        __syncthreads();
        if (wid == 0) {
            int w = wsum[lane];
#pragma unroll
            for (int o = 1; o < 32; o <<= 1) {
                int u = __shfl_up_sync(~0u, w, o);
                if (lane >= o) w += u;
            }
            wsum[lane] = w;
        }
        __syncthreads();
        int excl = v - dg + ((wid > 0) ? wsum[wid - 1] : 0) + s_carry;
        if (idx < N_NODES) {
            g_off[idx] = excl;
            g_cur[idx] = excl;
            g_dinv[idx] = rsqrtf((float)dg + 1.0f);
        }
        __syncthreads();
        if (tid == 0) s_carry += wsum[31];
        __syncthreads();
    }
    if (tid == 0) g_off[N_NODES] = s_carry;
}

// -------- fill CSR; re-zero g_deg for next call --------
__global__ __launch_bounds__(256) void k_fill(int E) {
    int e = blockIdx.x * 256 + threadIdx.x;
    int total = gridDim.x * 256;
    if (e < E) {
        int2 sd = g_edge[e];
        int pos = atomicAdd(&g_cur[sd.y], 1);
        g_csr[pos] = sd.x;
    }
    for (int i = e; i < N_NODES; i += total) g_deg[i] = 0;
}

// -------- GIN gather (fp16): aggrh[n] = half(x[n] + sum xh[csr]) -----------
__global__ __launch_bounds__(256) void k_gin_gather(const float* __restrict__ x) {
    int n = blockIdx.x * 8 + (threadIdx.x >> 5);
    if (n >= N_NODES) return;
    int lane = threadIdx.x & 31;
    int beg = __ldg(g_off + n), end = __ldg(g_off + n + 1);
    const uint2* xh = (const uint2*)g_xh;
    float4 a0 = __ldg((const float4*)x + (size_t)n * 32 + lane);
    float2 accA = make_float2(a0.x, a0.y);
    float2 accB = make_float2(a0.z, a0.w);
    int j = beg;
    for (; j + 8 <= end; j += 8) {
        int idx[8];
#pragma unroll
        for (int t = 0; t < 8; t++) idx[t] = __ldg(g_csr + j + t);
        uint2 v[8];
#pragma unroll
        for (int t = 0; t < 8; t++) v[t] = __ldg(xh + (size_t)idx[t] * 32 + lane);
#pragma unroll
        for (int t = 0; t < 8; t++) {
            float2 f0 = __half22float2(*(__half2*)&v[t].x);
            float2 f1 = __half22float2(*(__half2*)&v[t].y);
            accA.x += f0.x; accA.y += f0.y;
            accB.x += f1.x; accB.y += f1.y;
        }
    }
    for (; j < end; j++) {
        int s = __ldg(g_csr + j);
        uint2 v = __ldg(xh + (size_t)s * 32 + lane);
        float2 f0 = __half22float2(*(__half2*)&v.x);
        float2 f1 = __half22float2(*(__half2*)&v.y);
        accA.x += f0.x; accA.y += f0.y;
        accB.x += f1.x; accB.y += f1.y;
    }
    uint2 hx;
    *(__half2*)&hx.x = __floats2half2_rn(accA.x, accA.y);
    *(__half2*)&hx.y = __floats2half2_rn(accB.x, accB.y);
    *(uint2*)(g_aggrh + (size_t)n * 128 + lane * 4) = hx;
}

// ===================== HMMA plumbing =====================
__device__ __forceinline__ uint32_t smem_u32(const void* p) {
    return (uint32_t)__cvta_generic_to_shared(p);
}
__device__ __forceinline__ void ldmat_x4(uint32_t addr, uint32_t& r0, uint32_t& r1,
                                         uint32_t& r2, uint32_t& r3) {
    asm volatile("ldmatrix.sync.aligned.m8n8.x4.shared.b16 {%0,%1,%2,%3}, [%4];"
                 : "=r"(r0), "=r"(r1), "=r"(r2), "=r"(r3) : "r"(addr));
}
__device__ __forceinline__ void ldmat_x4_t(uint32_t addr, uint32_t& r0, uint32_t& r1,
                                           uint32_t& r2, uint32_t& r3) {
    asm volatile("ldmatrix.sync.aligned.m8n8.x4.trans.shared.b16 {%0,%1,%2,%3}, [%4];"
                 : "=r"(r0), "=r"(r1), "=r"(r2), "=r"(r3) : "r"(addr));
}
__device__ __forceinline__ void mma16816(float* c, uint32_t a0, uint32_t a1, uint32_t a2,
                                         uint32_t a3, uint32_t b0, uint32_t b1) {
    asm volatile(
        "mma.sync.aligned.m16n8k16.row.col.f32.f16.f16.f32 "
        "{%0,%1,%2,%3}, {%4,%5,%6,%7}, {%8,%9}, {%0,%1,%2,%3};"
        : "+f"(c[0]), "+f"(c[1]), "+f"(c[2]), "+f"(c[3])
        : "r"(a0), "r"(a1), "r"(a2), "r"(a3), "r"(b0), "r"(b1));
}

// one GEMM phase: C[8][4] += As[wm*16.., :] @ Ws[:, wn*64..]
__device__ __forceinline__ void mma_phase(const __half* As, const __half* Ws,
                                          int wm, int wn, int lane, float C[8][4]) {
#pragma unroll
    for (int t = 0; t < 8; t++) {
        C[t][0] = 0.f; C[t][1] = 0.f; C[t][2] = 0.f; C[t][3] = 0.f;
    }
    int l15 = lane & 15, l16 = lane >> 4;
    const __half* abase = As + (wm * 16 + l15) * 136 + l16 * 8;
    const __half* bbase = Ws + l15 * 136 + wn * 64 + l16 * 8;
#pragma unroll
    for (int k = 0; k < 8; k++) {
        uint32_t a0, a1, a2, a3;
        ldmat_x4(smem_u32(abase + k * 16), a0, a1, a2, a3);
#pragma unroll
        for (int t = 0; t < 4; t++) {
            uint32_t b0, b1, b2, b3;
            ldmat_x4_t(smem_u32(bbase + (k * 16) * 136 + t * 16), b0, b1, b2, b3);
            mma16816(C[2 * t], a0, a1, a2, a3, b0, b1);
            mma16816(C[2 * t + 1], a0, a1, a2, a3, b2, b3);
        }
    }
}

__device__ __forceinline__ void load_W_half(const float* __restrict__ W,
                                            __half* __restrict__ Ws, int tid, int nt) {
    for (int i = tid; i < 4096; i += nt) {
        float4 v = __ldg((const float4*)W + i);
        int k = i >> 5, c4 = i & 31;
        uint2 h;
        *(__half2*)&h.x = __floats2half2_rn(v.x, v.y);
        *(__half2*)&h.y = __floats2half2_rn(v.z, v.w);
        *(uint2*)(Ws + k * 136 + c4 * 4) = h;
    }
}

// ===================== 3-layer HMMA GEMM: 128 nodes/block, 512 threads ======
__global__ __launch_bounds__(512) void k_mlp_hmma(const float* __restrict__ W1,
                                                  const float* __restrict__ b1,
                                                  const float* __restrict__ gamma,
                                                  const float* __restrict__ beta,
                                                  const float* __restrict__ rmean,
                                                  const float* __restrict__ rvar,
                                                  const float* __restrict__ W2,
                                                  const float* __restrict__ b2,
                                                  const float* __restrict__ Wmu,
                                                  const float* __restrict__ bmu,
                                                  const float* __restrict__ Wls,
                                                  const float* __restrict__ bls,
                                                  float* __restrict__ out) {
    extern __shared__ char smraw[];
    __half* Ws = (__half*)smraw;                       // 34816 B
    __half* As = (__half*)(smraw + WS_HALFS * 2);      // 34816 B
    float* scale_s = (float*)(smraw + WS_HALFS * 2 + AS_HALFS * 2);
    float* shift_s = scale_s + 128;
    float* b2s = shift_s + 128;
    float* bcs = b2s + 128;

    int tid = threadIdx.x, lane = tid & 31, wid = tid >> 5;
    int node0 = blockIdx.x << 7;   // 128 nodes per block

    if (tid < 128) {
        float sc = gamma[tid] * rsqrtf(rvar[tid] + 1e-5f);
        scale_s[tid] = sc;
        shift_s[tid] = (b1[tid] - rmean[tid]) * sc + beta[tid];
        b2s[tid] = b2[tid];
        bcs[tid] = (tid < 64) ? bmu[tid] : bls[tid - 64];
    }
    load_W_half(W1, Ws, tid, 512);
    // load 128 aggr rows (fp16) coalesced
    for (int i = tid; i < 4096; i += 512) {
        int n = i >> 5, q = i & 31;
        int node = node0 + n;
        if (node > N_NODES - 1) node = N_NODES - 1;
        uint2 h = __ldg((const uint2*)(g_aggrh + (size_t)node * 128) + q);
        *(uint2*)(As + n * 136 + q * 4) = h;
    }
    __syncthreads();

    int wm = wid & 7, wn = wid >> 3;   // 8 m-tiles x 2 n-halves
    int r0 = wm * 16 + (lane >> 2);
    float C[8][4];

    // ---- phase 1: h1 = relu(BN(A @ W1)) ----
    mma_phase(As, Ws, wm, wn, lane, C);
    __syncthreads();
#pragma unroll
    for (int t = 0; t < 8; t++) {
        int c0 = wn * 64 + t * 8 + (lane & 3) * 2;
        float sc0 = scale_s[c0], sc1 = scale_s[c0 + 1];
        float sh0 = shift_s[c0], sh1 = shift_s[c0 + 1];
        *(__half2*)(As + r0 * 136 + c0) = __floats2half2_rn(
            fmaxf(C[t][0] * sc0 + sh0, 0.f), fmaxf(C[t][1] * sc1 + sh1, 0.f));
        *(__half2*)(As + (r0 + 8) * 136 + c0) = __floats2half2_rn(
            fmaxf(C[t][2] * sc0 + sh0, 0.f), fmaxf(C[t][3] * sc1 + sh1, 0.f));
    }
    load_W_half(W2, Ws, tid, 512);
    __syncthreads();

    // ---- phase 2: h2 = relu(A @ W2 + b2) ----
    mma_phase(As, Ws, wm, wn, lane, C);
    __syncthreads();
#pragma unroll
    for (int t = 0; t < 8; t++) {
        int c0 = wn * 64 + t * 8 + (lane & 3) * 2;
        float bb0 = b2s[c0], bb1 = b2s[c0 + 1];
        *(__half2*)(As + r0 * 136 + c0) = __floats2half2_rn(
            fmaxf(C[t][0] + bb0, 0.f), fmaxf(C[t][1] + bb1, 0.f));
        *(__half2*)(As + (r0 + 8) * 136 + c0) = __floats2half2_rn(
            fmaxf(C[t][2] + bb0, 0.f), fmaxf(C[t][3] + bb1, 0.f));
    }
    // load concatenated [Wmu|Wls] fp16
    for (int i = tid; i < 4096; i += 512) {
        int k = i >> 5, c4 = i & 31;
        float4 v = (c4 < 16) ? __ldg((const float4*)Wmu + k * 16 + c4)
                             : __ldg((const float4*)Wls + k * 16 + (c4 - 16));
        uint2 h;
        *(__half2*)&h.x = __floats2half2_rn(v.x, v.y);
        *(__half2*)&h.y = __floats2half2_rn(v.z, v.w);
        *(uint2*)(Ws + k * 136 + c4 * 4) = h;
    }
    __syncthreads();

    // ---- phase 3: xw = A @ [Wmu|Wls]; xwh = half(dinv*xw); out = dinv^2*xw + b
    mma_phase(As, Ws, wm, wn, lane, C);
    {
        int nodeA = node0 + r0;
        int nodeB = nodeA + 8;
        bool okA = nodeA < N_NODES, okB = nodeB < N_NODES;
        float dnA = okA ? g_dinv[nodeA] : 0.f;
        float dnB = okB ? g_dinv[nodeB] : 0.f;
#pragma unroll
        for (int t = 0; t < 8; t++) {
            int c0 = wn * 64 + t * 8 + (lane & 3) * 2;
            float bb0 = bcs[c0], bb1 = bcs[c0 + 1];
            if (okA) {
                float x0 = dnA * C[t][0], x1 = dnA * C[t][1];
                *(__half2*)(g_xwh + (size_t)nodeA * 128 + c0) = __floats2half2_rn(x0, x1);
                float* ob = (c0 < 64) ? (out + (size_t)nodeA * 64 + c0)
                                      : (out + (size_t)N_NODES * 64 + (size_t)nodeA * 64 + (c0 - 64));
                *(float2*)ob = make_float2(dnA * x0 + bb0, dnA * x1 + bb1);
            }
            if (okB) {
                float x0 = dnB * C[t][2], x1 = dnB * C[t][3];
                *(__half2*)(g_xwh + (size_t)nodeB * 128 + c0) = __floats2half2_rn(x0, x1);
                float* ob = (c0 < 64) ? (out + (size_t)nodeB * 64 + c0)
                                      : (out + (size_t)N_NODES * 64 + (size_t)nodeB * 64 + (c0 - 64));
                *(float2*)ob = make_float2(dnB * x0 + bb0, dnB * x1 + bb1);
            }
        }
    }
}

// -------- GCN gather (fp16 rows): out[n] += dinv[n] * sum xwh[csr] ---------
__global__ __launch_bounds__(256) void k_gcn_gather(float* __restrict__ out) {
    int n = blockIdx.x * 8 + (threadIdx.x >> 5);
    if (n >= N_NODES) return;
    int lane = threadIdx.x & 31;
    int beg = __ldg(g_off + n), end = __ldg(g_off + n + 1);
    const uint2* xh = (const uint2*)g_xwh;
    float2 accA = make_float2(0.f, 0.f), accB = make_float2(0.f, 0.f);
    int j = beg;
    for (; j + 8 <= end; j += 8) {
        int idx[8];
#pragma unroll
        for (int t = 0; t < 8; t++) idx[t] = __ldg(g_csr + j + t);
        uint2 v[8];
#pragma unroll
        for (int t = 0; t < 8; t++) v[t] = __ldg(xh + (size_t)idx[t] * 32 + lane);
#pragma unroll
        for (int t = 0; t < 8; t++) {
            float2 f0 = __half22float2(*(__half2*)&v[t].x);
            float2 f1 = __half22float2(*(__half2*)&v[t].y);
            accA.x += f0.x; accA.y += f0.y;
            accB.x += f1.x; accB.y += f1.y;
        }
    }
    for (; j < end; j++) {
        int s = __ldg(g_csr + j);
        uint2 v = __ldg(xh + (size_t)s * 32 + lane);
        float2 f0 = __half22float2(*(__half2*)&v.x);
        float2 f1 = __half22float2(*(__half2*)&v.y);
        accA.x += f0.x; accA.y += f0.y;
        accB.x += f1.x; accB.y += f1.y;
    }
    float dn = g_dinv[n];
    int c0 = lane * 4;
    float* ob = (c0 < 64) ? (out + (size_t)n * 64 + c0)
                          : (out + (size_t)N_NODES * 64 + (size_t)n * 64 + (c0 - 64));
    float4 cur = *(float4*)ob;
    cur.x += dn * accA.x; cur.y += dn * accA.y;
    cur.z += dn * accB.x; cur.w += dn * accB.y;
    *(float4*)ob = cur;
}

extern "C" void kernel_launch(void* const* d_in, const int* in_sizes, int n_in,
                              void* d_out, int out_size) {
    const float* x     = (const float*)d_in[0];
    const void*  ei    = (const void*)d_in[1];
    const float* W1    = (const float*)d_in[2];
    const float* b1    = (const float*)d_in[3];
    const float* gamma = (const float*)d_in[4];
    const float* beta  = (const float*)d_in[5];
    const float* rmean = (const float*)d_in[6];
    const float* rvar  = (const float*)d_in[7];
    const float* W2    = (const float*)d_in[8];
    const float* b2    = (const float*)d_in[9];
    const float* Wmu   = (const float*)d_in[10];
    const float* bmu   = (const float*)d_in[11];
    const float* Wls   = (const float*)d_in[12];
    const float* bls   = (const float*)d_in[13];
    float* out = (float*)d_out;

    int E = in_sizes[1] / 2;

    const int SMEM = WS_HALFS * 2 + AS_HALFS * 2 + 512 * 4;  // 71680 B
    cudaFuncSetAttribute(k_mlp_hmma, cudaFuncAttributeMaxDynamicSharedMemorySize, SMEM);

    int eb = (E + 255) / 256;
    int nb = (N_NODES + 7) / 8;
    int mb = (N_NODES + 127) / 128;

    k_count<<<eb, 256>>>(ei, x, E);                                    // 0
    k_scan<<<1, 1024>>>();                                             // 1
    k_fill<<<eb, 256>>>(E);                                            // 2
    k_gin_gather<<<nb, 256>>>(x);                                      // 3 <- profiled
    k_mlp_hmma<<<mb, 512, SMEM>>>(W1, b1, gamma, beta, rmean, rvar,    // 4
                                  W2, b2, Wmu, bmu, Wls, bls, out);
    k_gcn_gather<<<nb, 256>>>(out);                                    // 5
}

// round 11
// speedup vs baseline: 3.5285x; 1.0318x over previous
#include <cuda_runtime.h>
#include <cuda_fp16.h>
#include <cstdint>

#define N_NODES 100000
#define DIMH 128
#define E_CAP 4000000
#define WS_HALFS (128 * 136)
#define AS_HALFS (128 * 136)

// -------- scratch (device globals; no allocation allowed) --------
__device__ __align__(16) __half g_xh[(size_t)N_NODES * DIMH];    // fp16 copy of x
__device__ __align__(16) __half g_aggrh[(size_t)N_NODES * DIMH]; // fp16 x+sum(neigh)
__device__ __align__(16) __half g_xwh[(size_t)N_NODES * DIMH];   // fp16 dinv-scaled xw
__device__ __align__(16) __half g_w1h[WS_HALFS];  // pre-swizzled fp16 W1
__device__ __align__(16) __half g_w2h[WS_HALFS];  // pre-swizzled fp16 W2
__device__ __align__(16) __half g_wch[WS_HALFS];  // pre-swizzled fp16 [Wmu|Wls]
__device__ float g_dinv[N_NODES];
__device__ int   g_deg[N_NODES];   // zero at load; k_fill re-zeros each call
__device__ int   g_off[N_NODES + 1];
__device__ int   g_cur[N_NODES];
__device__ int   g_csr[E_CAP];
__device__ int2  g_edge[E_CAP];

// -------- count + edge conversion + x->fp16 + W->fp16 (pre-swizzled) -------
__global__ __launch_bounds__(256) void k_count(const void* __restrict__ ei,
                                               const float* __restrict__ x,
                                               const float* __restrict__ W1,
                                               const float* __restrict__ W2,
                                               const float* __restrict__ Wmu,
                                               const float* __restrict__ Wls,
                                               int E) {
    __shared__ int s_is64;
    if (threadIdx.x < 32) {
        unsigned w = __ldg((const unsigned*)ei + threadIdx.x * 2 + 1);
        unsigned b = __ballot_sync(0xffffffffu, w != 0u);
        if (threadIdx.x == 0) s_is64 = (b == 0u);
    }
    __syncthreads();
    int gid = blockIdx.x * 256 + threadIdx.x;
    int total = gridDim.x * 256;
    if (gid < E) {
        int s, d;
        if (s_is64) {
            s = (int)__ldg((const long long*)ei + gid);
            d = (int)__ldg((const long long*)ei + E + gid);
        } else {
            s = __ldg((const int*)ei + gid);
            d = __ldg((const int*)ei + E + gid);
        }
        g_edge[gid] = make_int2(s, d);
        atomicAdd(&g_deg[d], 1);
    }
    const float2* x2 = (const float2*)x;
    __half2* xh2 = (__half2*)g_xh;
    const int NH2 = N_NODES * (DIMH / 2);
    for (int i = gid; i < NH2; i += total) {
        float2 v = __ldg(x2 + i);
        xh2[i] = __floats2half2_rn(v.x, v.y);
    }
    // weights -> fp16 in smem-image layout (row k at k*136, float4 chunk c4 at c4*4)
    for (int i = gid; i < 3 * 4096; i += total) {
        int w = i >> 12, j = i & 4095;
        int k = j >> 5, c4 = j & 31;
        float4 v;
        __half* dst;
        if (w == 0)      { v = __ldg((const float4*)W1 + j); dst = g_w1h; }
        else if (w == 1) { v = __ldg((const float4*)W2 + j); dst = g_w2h; }
        else {
            v = (c4 < 16) ? __ldg((const float4*)Wmu + k * 16 + c4)
                          : __ldg((const float4*)Wls + k * 16 + (c4 - 16));
            dst = g_wch;
        }
        uint2 h;
        *(__half2*)&h.x = __floats2half2_rn(v.x, v.y);
        *(__half2*)&h.y = __floats2half2_rn(v.z, v.w);
        *(uint2*)(dst + k * 136 + c4 * 4) = h;
    }
}

// -------- coalesced tiled single-block scan (+ dinv) --------
__global__ __launch_bounds__(1024) void k_scan() {
    __shared__ int wsum[32];
    __shared__ int s_carry;
    int tid = threadIdx.x, lane = tid & 31, wid = tid >> 5;
    if (tid == 0) s_carry = 0;
    __syncthreads();
    const int NT = (N_NODES + 1023) / 1024;
    for (int t = 0; t < NT; t++) {
        int idx = t * 1024 + tid;
        int dg = (idx < N_NODES) ? g_deg[idx] : 0;
        int v = dg;
#pragma unroll
        for (int o = 1; o < 32; o <<= 1) {
            int u = __shfl_up_sync(~0u, v, o);
            if (lane >= o) v += u;
        }
        if (lane == 31) wsum[wid] = v;
        __syncthreads();
        if (wid == 0) {
            int w = wsum[lane];
#pragma unroll
            for (int o = 1; o < 32; o <<= 1) {
                int u = __shfl_up_sync(~0u, w, o);
                if (lane >= o) w += u;
            }
            wsum[lane] = w;
        }
        __syncthreads();
        int excl = v - dg + ((wid > 0) ? wsum[wid - 1] : 0) + s_carry;
        if (idx < N_NODES) {
            g_off[idx] = excl;
            g_cur[idx] = excl;
            g_dinv[idx] = rsqrtf((float)dg + 1.0f);
        }
        __syncthreads();
        if (tid == 0) s_carry += wsum[31];
        __syncthreads();
    }
    if (tid == 0) g_off[N_NODES] = s_carry;
}

// -------- fill CSR; re-zero g_deg for next call --------
__global__ __launch_bounds__(256) void k_fill(int E) {
    int e = blockIdx.x * 256 + threadIdx.x;
    int total = gridDim.x * 256;
    if (e < E) {
        int2 sd = g_edge[e];
        int pos = atomicAdd(&g_cur[sd.y], 1);
        g_csr[pos] = sd.x;
    }
    for (int i = e; i < N_NODES; i += total) g_deg[i] = 0;
}

// -------- GIN gather (fp16): aggrh[n] = half(x[n] + sum xh[csr]) -----------
__global__ __launch_bounds__(256) void k_gin_gather(const float* __restrict__ x) {
    int n = blockIdx.x * 8 + (threadIdx.x >> 5);
    if (n >= N_NODES) return;
    int lane = threadIdx.x & 31;
    int beg = __ldg(g_off + n), end = __ldg(g_off + n + 1);
    const uint2* xh = (const uint2*)g_xh;
    float4 a0 = __ldg((const float4*)x + (size_t)n * 32 + lane);
    float2 accA = make_float2(a0.x, a0.y);
    float2 accB = make_float2(a0.z, a0.w);
    int j = beg;
    for (; j + 8 <= end; j += 8) {
        int idx[8];
#pragma unroll
        for (int t = 0; t < 8; t++) idx[t] = __ldg(g_csr + j + t);
        uint2 v[8];
#pragma unroll
        for (int t = 0; t < 8; t++) v[t] = __ldg(xh + (size_t)idx[t] * 32 + lane);
#pragma unroll
        for (int t = 0; t < 8; t++) {
            float2 f0 = __half22float2(*(__half2*)&v[t].x);
            float2 f1 = __half22float2(*(__half2*)&v[t].y);
            accA.x += f0.x; accA.y += f0.y;
            accB.x += f1.x; accB.y += f1.y;
        }
    }
    for (; j < end; j++) {
        int s = __ldg(g_csr + j);
        uint2 v = __ldg(xh + (size_t)s * 32 + lane);
        float2 f0 = __half22float2(*(__half2*)&v.x);
        float2 f1 = __half22float2(*(__half2*)&v.y);
        accA.x += f0.x; accA.y += f0.y;
        accB.x += f1.x; accB.y += f1.y;
    }
    uint2 hx;
    *(__half2*)&hx.x = __floats2half2_rn(accA.x, accA.y);
    *(__half2*)&hx.y = __floats2half2_rn(accB.x, accB.y);
    *(uint2*)(g_aggrh + (size_t)n * 128 + lane * 4) = hx;
}

// ===================== HMMA plumbing =====================
__device__ __forceinline__ uint32_t smem_u32(const void* p) {
    return (uint32_t)__cvta_generic_to_shared(p);
}
__device__ __forceinline__ void ldmat_x4(uint32_t addr, uint32_t& r0, uint32_t& r1,
                                         uint32_t& r2, uint32_t& r3) {
    asm volatile("ldmatrix.sync.aligned.m8n8.x4.shared.b16 {%0,%1,%2,%3}, [%4];"
                 : "=r"(r0), "=r"(r1), "=r"(r2), "=r"(r3) : "r"(addr));
}
__device__ __forceinline__ void ldmat_x4_t(uint32_t addr, uint32_t& r0, uint32_t& r1,
                                           uint32_t& r2, uint32_t& r3) {
    asm volatile("ldmatrix.sync.aligned.m8n8.x4.trans.shared.b16 {%0,%1,%2,%3}, [%4];"
                 : "=r"(r0), "=r"(r1), "=r"(r2), "=r"(r3) : "r"(addr));
}
__device__ __forceinline__ void mma16816(float* c, uint32_t a0, uint32_t a1, uint32_t a2,
                                         uint32_t a3, uint32_t b0, uint32_t b1) {
    asm volatile(
        "mma.sync.aligned.m16n8k16.row.col.f32.f16.f16.f32 "
        "{%0,%1,%2,%3}, {%4,%5,%6,%7}, {%8,%9}, {%0,%1,%2,%3};"
        : "+f"(c[0]), "+f"(c[1]), "+f"(c[2]), "+f"(c[3])
        : "r"(a0), "r"(a1), "r"(a2), "r"(a3), "r"(b0), "r"(b1));
}

// one GEMM phase: C[8][4] += As[wm*16.., :] @ Ws[:, wn*64..]
__device__ __forceinline__ void mma_phase(const __half* As, const __half* Ws,
                                          int wm, int wn, int lane, float C[8][4]) {
#pragma unroll
    for (int t = 0; t < 8; t++) {
        C[t][0] = 0.f; C[t][1] = 0.f; C[t][2] = 0.f; C[t][3] = 0.f;
    }
    int l15 = lane & 15, l16 = lane >> 4;
    const __half* abase = As + (wm * 16 + l15) * 136 + l16 * 8;
    const __half* bbase = Ws + l15 * 136 + wn * 64 + l16 * 8;
#pragma unroll
    for (int k = 0; k < 8; k++) {
        uint32_t a0, a1, a2, a3;
        ldmat_x4(smem_u32(abase + k * 16), a0, a1, a2, a3);
#pragma unroll
        for (int t = 0; t < 4; t++) {
            uint32_t b0, b1, b2, b3;
            ldmat_x4_t(smem_u32(bbase + (k * 16) * 136 + t * 16), b0, b1, b2, b3);
            mma16816(C[2 * t], a0, a1, a2, a3, b0, b1);
            mma16816(C[2 * t + 1], a0, a1, a2, a3, b2, b3);
        }
    }
}

// copy pre-swizzled fp16 W image into smem (plain uint4 memcpy)
__device__ __forceinline__ void copy_W(const __half* __restrict__ src,
                                       __half* __restrict__ Ws, int tid) {
    const uint4* s4 = (const uint4*)src;
    uint4* d4 = (uint4*)Ws;
    for (int i = tid; i < WS_HALFS / 8; i += 512) d4[i] = __ldg(s4 + i);
}

// ===================== 3-layer HMMA GEMM: 128 nodes/block, 512 threads ======
__global__ __launch_bounds__(512, 2) void k_mlp_hmma(const float* __restrict__ b1,
                                                     const float* __restrict__ gamma,
                                                     const float* __restrict__ beta,
                                                     const float* __restrict__ rmean,
                                                     const float* __restrict__ rvar,
                                                     const float* __restrict__ b2,
                                                     const float* __restrict__ bmu,
                                                     const float* __restrict__ bls,
                                                     float* __restrict__ out) {
    extern __shared__ char smraw[];
    __half* Ws = (__half*)smraw;                       // 34816 B
    __half* As = (__half*)(smraw + WS_HALFS * 2);      // 34816 B
    float* scale_s = (float*)(smraw + WS_HALFS * 2 + AS_HALFS * 2);
    float* shift_s = scale_s + 128;
    float* b2s = shift_s + 128;
    float* bcs = b2s + 128;

    int tid = threadIdx.x, lane = tid & 31, wid = tid >> 5;
    int node0 = blockIdx.x << 7;   // 128 nodes per block

    if (tid < 128) {
        float sc = gamma[tid] * rsqrtf(rvar[tid] + 1e-5f);
        scale_s[tid] = sc;
        shift_s[tid] = (b1[tid] - rmean[tid]) * sc + beta[tid];
        b2s[tid] = b2[tid];
        bcs[tid] = (tid < 64) ? bmu[tid] : bls[tid - 64];
    }
    copy_W(g_w1h, Ws, tid);
    // load 128 aggr rows (fp16) coalesced
    for (int i = tid; i < 4096; i += 512) {
        int n = i >> 5, q = i & 31;
        int node = node0 + n;
        if (node > N_NODES - 1) node = N_NODES - 1;
        uint2 h = __ldg((const uint2*)(g_aggrh + (size_t)node * 128) + q);
        *(uint2*)(As + n * 136 + q * 4) = h;
    }
    __syncthreads();

    int wm = wid & 7, wn = wid >> 3;   // 8 m-tiles x 2 n-halves
    int r0 = wm * 16 + (lane >> 2);
    float C[8][4];

    // ---- phase 1: h1 = relu(BN(A @ W1)) ----
    mma_phase(As, Ws, wm, wn, lane, C);
    __syncthreads();
#pragma unroll
    for (int t = 0; t < 8; t++) {
        int c0 = wn * 64 + t * 8 + (lane & 3) * 2;
        float sc0 = scale_s[c0], sc1 = scale_s[c0 + 1];
        float sh0 = shift_s[c0], sh1 = shift_s[c0 + 1];
        *(__half2*)(As + r0 * 136 + c0) = __floats2half2_rn(
            fmaxf(C[t][0] * sc0 + sh0, 0.f), fmaxf(C[t][1] * sc1 + sh1, 0.f));
        *(__half2*)(As + (r0 + 8) * 136 + c0) = __floats2half2_rn(
            fmaxf(C[t][2] * sc0 + sh0, 0.f), fmaxf(C[t][3] * sc1 + sh1, 0.f));
    }
    copy_W(g_w2h, Ws, tid);
    __syncthreads();

    // ---- phase 2: h2 = relu(A @ W2 + b2) ----
    mma_phase(As, Ws, wm, wn, lane, C);
    __syncthreads();
#pragma unroll
    for (int t = 0; t < 8; t++) {
        int c0 = wn * 64 + t * 8 + (lane & 3) * 2;
        float bb0 = b2s[c0], bb1 = b2s[c0 + 1];
        *(__half2*)(As + r0 * 136 + c0) = __floats2half2_rn(
            fmaxf(C[t][0] + bb0, 0.f), fmaxf(C[t][1] + bb1, 0.f));
        *(__half2*)(As + (r0 + 8) * 136 + c0) = __floats2half2_rn(
            fmaxf(C[t][2] + bb0, 0.f), fmaxf(C[t][3] + bb1, 0.f));
    }
    copy_W(g_wch, Ws, tid);
    __syncthreads();

    // ---- phase 3: xw = A @ [Wmu|Wls]; xwh = half(dinv*xw); out = dinv^2*xw + b
    mma_phase(As, Ws, wm, wn, lane, C);
    {
        int nodeA = node0 + r0;
        int nodeB = nodeA + 8;
        bool okA = nodeA < N_NODES, okB = nodeB < N_NODES;
        float dnA = okA ? g_dinv[nodeA] : 0.f;
        float dnB = okB ? g_dinv[nodeB] : 0.f;
#pragma unroll
        for (int t = 0; t < 8; t++) {
            int c0 = wn * 64 + t * 8 + (lane & 3) * 2;
            float bb0 = bcs[c0], bb1 = bcs[c0 + 1];
            if (okA) {
                float x0 = dnA * C[t][0], x1 = dnA * C[t][1];
                *(__half2*)(g_xwh + (size_t)nodeA * 128 + c0) = __floats2half2_rn(x0, x1);
                float* ob = (c0 < 64) ? (out + (size_t)nodeA * 64 + c0)
                                      : (out + (size_t)N_NODES * 64 + (size_t)nodeA * 64 + (c0 - 64));
                *(float2*)ob = make_float2(dnA * x0 + bb0, dnA * x1 + bb1);
            }
            if (okB) {
                float x0 = dnB * C[t][2], x1 = dnB * C[t][3];
                *(__half2*)(g_xwh + (size_t)nodeB * 128 + c0) = __floats2half2_rn(x0, x1);
                float* ob = (c0 < 64) ? (out + (size_t)nodeB * 64 + c0)
                                      : (out + (size_t)N_NODES * 64 + (size_t)nodeB * 64 + (c0 - 64));
                *(float2*)ob = make_float2(dnB * x0 + bb0, dnB * x1 + bb1);
            }
        }
    }
}

// -------- GCN gather (fp16 rows): out[n] += dinv[n] * sum xwh[csr] ---------
__global__ __launch_bounds__(256) void k_gcn_gather(float* __restrict__ out) {
    int n = blockIdx.x * 8 + (threadIdx.x >> 5);
    if (n >= N_NODES) return;
    int lane = threadIdx.x & 31;
    int beg = __ldg(g_off + n), end = __ldg(g_off + n + 1);
    const uint2* xh = (const uint2*)g_xwh;
    float2 accA = make_float2(0.f, 0.f), accB = make_float2(0.f, 0.f);
    int j = beg;
    for (; j + 8 <= end; j += 8) {
        int idx[8];
#pragma unroll
        for (int t = 0; t < 8; t++) idx[t] = __ldg(g_csr + j + t);
        uint2 v[8];
#pragma unroll
        for (int t = 0; t < 8; t++) v[t] = __ldg(xh + (size_t)idx[t] * 32 + lane);
#pragma unroll
        for (int t = 0; t < 8; t++) {
            float2 f0 = __half22float2(*(__half2*)&v[t].x);
            float2 f1 = __half22float2(*(__half2*)&v[t].y);
            accA.x += f0.x; accA.y += f0.y;
            accB.x += f1.x; accB.y += f1.y;
        }
    }
    for (; j < end; j++) {
        int s = __ldg(g_csr + j);
        uint2 v = __ldg(xh + (size_t)s * 32 + lane);
        float2 f0 = __half22float2(*(__half2*)&v.x);
        float2 f1 = __half22float2(*(__half2*)&v.y);
        accA.x += f0.x; accA.y += f0.y;
        accB.x += f1.x; accB.y += f1.y;
    }
    float dn = g_dinv[n];
    int c0 = lane * 4;
    float* ob = (c0 < 64) ? (out + (size_t)n * 64 + c0)
                          : (out + (size_t)N_NODES * 64 + (size_t)n * 64 + (c0 - 64));
    float4 cur = *(float4*)ob;
    cur.x += dn * accA.x; cur.y += dn * accA.y;
    cur.z += dn * accB.x; cur.w += dn * accB.y;
    *(float4*)ob = cur;
}

extern "C" void kernel_launch(void* const* d_in, const int* in_sizes, int n_in,
                              void* d_out, int out_size) {
    const float* x     = (const float*)d_in[0];
    const void*  ei    = (const void*)d_in[1];
    const float* W1    = (const float*)d_in[2];
    const float* b1    = (const float*)d_in[3];
    const float* gamma = (const float*)d_in[4];
    const float* beta  = (const float*)d_in[5];
    const float* rmean = (const float*)d_in[6];
    const float* rvar  = (const float*)d_in[7];
    const float* W2    = (const float*)d_in[8];
    const float* b2    = (const float*)d_in[9];
    const float* Wmu   = (const float*)d_in[10];
    const float* bmu   = (const float*)d_in[11];
    const float* Wls   = (const float*)d_in[12];
    const float* bls   = (const float*)d_in[13];
    float* out = (float*)d_out;

    int E = in_sizes[1] / 2;

    const int SMEM = WS_HALFS * 2 + AS_HALFS * 2 + 512 * 4;  // 71680 B
    cudaFuncSetAttribute(k_mlp_hmma, cudaFuncAttributeMaxDynamicSharedMemorySize, SMEM);

    int eb = (E + 255) / 256;
    int nb = (N_NODES + 7) / 8;
    int mb = (N_NODES + 127) / 128;

    k_count<<<eb, 256>>>(ei, x, W1, W2, Wmu, Wls, E);                  // 0
    k_scan<<<1, 1024>>>();                                             // 1
    k_fill<<<eb, 256>>>(E);                                            // 2
    k_gin_gather<<<nb, 256>>>(x);                                      // 3 <- profiled
    k_mlp_hmma<<<mb, 512, SMEM>>>(b1, gamma, beta, rmean, rvar,        // 4
                                  b2, bmu, bls, out);
    k_gcn_gather<<<nb, 256>>>(out);                                    // 5
}

// round 13
// speedup vs baseline: 3.8754x; 1.0983x over previous
#include <cuda_runtime.h>
#include <cuda_fp16.h>
#include <cstdint>

#define N_NODES 100000
#define DIMH 128
#define E_CAP 4000000
#define WS_HALFS (128 * 136)
#define AS_HALFS (128 * 136)

// -------- scratch (device globals; no allocation allowed) --------
__device__ __align__(16) __half g_xh[(size_t)N_NODES * DIMH];    // fp16 copy of x
__device__ __align__(16) __half g_aggrh[(size_t)N_NODES * DIMH]; // fp16 x+sum(neigh)
__device__ __align__(16) __half g_xwh[(size_t)N_NODES * DIMH];   // fp16 dinv-scaled xw
__device__ __align__(16) __half g_w1h[WS_HALFS];  // pre-swizzled fp16 W1
__device__ __align__(16) __half g_w2h[WS_HALFS];  // pre-swizzled fp16 W2
__device__ __align__(16) __half g_wch[WS_HALFS];  // pre-swizzled fp16 [Wmu|Wls]
__device__ float g_dinv[N_NODES];
__device__ int   g_deg[N_NODES];   // zero at load; k_fill re-zeros each call
__device__ int   g_off[N_NODES + 1];
__device__ int   g_cur[N_NODES];
__device__ int   g_csr[E_CAP];
__device__ int2  g_edge[E_CAP];

// -------- count + edge conversion + x->fp16 + W->fp16 (pre-swizzled) -------
__global__ __launch_bounds__(256) void k_count(const void* __restrict__ ei,
                                               const float* __restrict__ x,
                                               const float* __restrict__ W1,
                                               const float* __restrict__ W2,
                                               const float* __restrict__ Wmu,
                                               const float* __restrict__ Wls,
                                               int E) {
    __shared__ int s_is64;
    if (threadIdx.x < 32) {
        unsigned w = __ldg((const unsigned*)ei + threadIdx.x * 2 + 1);
        unsigned b = __ballot_sync(0xffffffffu, w != 0u);
        if (threadIdx.x == 0) s_is64 = (b == 0u);
    }
    __syncthreads();
    int gid = blockIdx.x * 256 + threadIdx.x;
    int total = gridDim.x * 256;
    if (gid < E) {
        int s, d;
        if (s_is64) {
            s = (int)__ldg((const long long*)ei + gid);
            d = (int)__ldg((const long long*)ei + E + gid);
        } else {
            s = __ldg((const int*)ei + gid);
            d = __ldg((const int*)ei + E + gid);
        }
        g_edge[gid] = make_int2(s, d);
        atomicAdd(&g_deg[d], 1);
    }
    const float2* x2 = (const float2*)x;
    __half2* xh2 = (__half2*)g_xh;
    const int NH2 = N_NODES * (DIMH / 2);
    for (int i = gid; i < NH2; i += total) {
        float2 v = __ldg(x2 + i);
        xh2[i] = __floats2half2_rn(v.x, v.y);
    }
    // weights -> fp16 in smem-image layout (row k at k*136, float4 chunk c4 at c4*4)
    for (int i = gid; i < 3 * 4096; i += total) {
        int w = i >> 12, j = i & 4095;
        int k = j >> 5, c4 = j & 31;
        float4 v;
        __half* dst;
        if (w == 0)      { v = __ldg((const float4*)W1 + j); dst = g_w1h; }
        else if (w == 1) { v = __ldg((const float4*)W2 + j); dst = g_w2h; }
        else {
            v = (c4 < 16) ? __ldg((const float4*)Wmu + k * 16 + c4)
                          : __ldg((const float4*)Wls + k * 16 + (c4 - 16));
            dst = g_wch;
        }
        uint2 h;
        *(__half2*)&h.x = __floats2half2_rn(v.x, v.y);
        *(__half2*)&h.y = __floats2half2_rn(v.z, v.w);
        *(uint2*)(dst + k * 136 + c4 * 4) = h;
    }
}

// -------- coalesced tiled single-block scan (+ dinv) --------
__global__ __launch_bounds__(1024) void k_scan() {
    __shared__ int wsum[32];
    __shared__ int s_carry;
    int tid = threadIdx.x, lane = tid & 31, wid = tid >> 5;
    if (tid == 0) s_carry = 0;
    __syncthreads();
    const int NT = (N_NODES + 1023) / 1024;
    for (int t = 0; t < NT; t++) {
        int idx = t * 1024 + tid;
        int dg = (idx < N_NODES) ? g_deg[idx] : 0;
        int v = dg;
#pragma unroll
        for (int o = 1; o < 32; o <<= 1) {
            int u = __shfl_up_sync(~0u, v, o);
            if (lane >= o) v += u;
        }
        if (lane == 31) wsum[wid] = v;
        __syncthreads();
        if (wid == 0) {
            int w = wsum[lane];
#pragma unroll
            for (int o = 1; o < 32; o <<= 1) {
                int u = __shfl_up_sync(~0u, w, o);
                if (lane >= o) w += u;
            }
            wsum[lane] = w;
        }
        __syncthreads();
        int excl = v - dg + ((wid > 0) ? wsum[wid - 1] : 0) + s_carry;
        if (idx < N_NODES) {
            g_off[idx] = excl;
            g_cur[idx] = excl;
            g_dinv[idx] = rsqrtf((float)dg + 1.0f);
        }
        __syncthreads();
        if (tid == 0) s_carry += wsum[31];
        __syncthreads();
    }
    if (tid == 0) g_off[N_NODES] = s_carry;
}

// -------- fill CSR; re-zero g_deg for next call --------
__global__ __launch_bounds__(256) void k_fill(int E) {
    int e = blockIdx.x * 256 + threadIdx.x;
    int total = gridDim.x * 256;
    if (e < E) {
        int2 sd = g_edge[e];
        int pos = atomicAdd(&g_cur[sd.y], 1);
        g_csr[pos] = sd.x;
    }
    for (int i = e; i < N_NODES; i += total) g_deg[i] = 0;
}

// -------- GIN gather (fp16): aggrh[n] = half(xh[n] + sum xh[csr]) ----------
__global__ __launch_bounds__(256) void k_gin_gather() {
    int n = blockIdx.x * 8 + (threadIdx.x >> 5);
    if (n >= N_NODES) return;
    int lane = threadIdx.x & 31;
    int beg = __ldg(g_off + n), end = __ldg(g_off + n + 1);
    const uint2* xh = (const uint2*)g_xh;
    uint2 sh = __ldg(xh + (size_t)n * 32 + lane);  // self term (fp16)
    float2 accA = __half22float2(*(__half2*)&sh.x);
    float2 accB = __half22float2(*(__half2*)&sh.y);
    int j = beg;
    for (; j + 8 <= end; j += 8) {
        int idx[8];
#pragma unroll
        for (int t = 0; t < 8; t++) idx[t] = __ldg(g_csr + j + t);
        uint2 v[8];
#pragma unroll
        for (int t = 0; t < 8; t++) v[t] = __ldg(xh + (size_t)idx[t] * 32 + lane);
#pragma unroll
        for (int t = 0; t < 8; t++) {
            float2 f0 = __half22float2(*(__half2*)&v[t].x);
            float2 f1 = __half22float2(*(__half2*)&v[t].y);
            accA.x += f0.x; accA.y += f0.y;
            accB.x += f1.x; accB.y += f1.y;
        }
    }
    for (; j < end; j++) {
        int s = __ldg(g_csr + j);
        uint2 v = __ldg(xh + (size_t)s * 32 + lane);
        float2 f0 = __half22float2(*(__half2*)&v.x);
        float2 f1 = __half22float2(*(__half2*)&v.y);
        accA.x += f0.x; accA.y += f0.y;
        accB.x += f1.x; accB.y += f1.y;
    }
    uint2 hx;
    *(__half2*)&hx.x = __floats2half2_rn(accA.x, accA.y);
    *(__half2*)&hx.y = __floats2half2_rn(accB.x, accB.y);
    *(uint2*)(g_aggrh + (size_t)n * 128 + lane * 4) = hx;
}

// ===================== HMMA plumbing =====================
__device__ __forceinline__ uint32_t smem_u32(const void* p) {
    return (uint32_t)__cvta_generic_to_shared(p);
}
__device__ __forceinline__ void ldmat_x4(uint32_t addr, uint32_t& r0, uint32_t& r1,
                                         uint32_t& r2, uint32_t& r3) {
    asm volatile("ldmatrix.sync.aligned.m8n8.x4.shared.b16 {%0,%1,%2,%3}, [%4];"
                 : "=r"(r0), "=r"(r1), "=r"(r2), "=r"(r3) : "r"(addr));
}
__device__ __forceinline__ void ldmat_x4_t(uint32_t addr, uint32_t& r0, uint32_t& r1,
                                           uint32_t& r2, uint32_t& r3) {
    asm volatile("ldmatrix.sync.aligned.m8n8.x4.trans.shared.b16 {%0,%1,%2,%3}, [%4];"
                 : "=r"(r0), "=r"(r1), "=r"(r2), "=r"(r3) : "r"(addr));
}
__device__ __forceinline__ void mma16816(float* c, uint32_t a0, uint32_t a1, uint32_t a2,
                                         uint32_t a3, uint32_t b0, uint32_t b1) {
    asm volatile(
        "mma.sync.aligned.m16n8k16.row.col.f32.f16.f16.f32 "
        "{%0,%1,%2,%3}, {%4,%5,%6,%7}, {%8,%9}, {%0,%1,%2,%3};"
        : "+f"(c[0]), "+f"(c[1]), "+f"(c[2]), "+f"(c[3])
        : "r"(a0), "r"(a1), "r"(a2), "r"(a3), "r"(b0), "r"(b1));
}

// one GEMM phase: C[8][4] += As[wm*16.., :] @ Ws[:, wn*64..]
__device__ __forceinline__ void mma_phase(const __half* As, const __half* Ws,
                                          int wm, int wn, int lane, float C[8][4]) {
#pragma unroll
    for (int t = 0; t < 8; t++) {
        C[t][0] = 0.f; C[t][1] = 0.f; C[t][2] = 0.f; C[t][3] = 0.f;
    }
    int l15 = lane & 15, l16 = lane >> 4;
    const __half* abase = As + (wm * 16 + l15) * 136 + l16 * 8;
    const __half* bbase = Ws + l15 * 136 + wn * 64 + l16 * 8;
#pragma unroll
    for (int k = 0; k < 8; k++) {
        uint32_t a0, a1, a2, a3;
        ldmat_x4(smem_u32(abase + k * 16), a0, a1, a2, a3);
#pragma unroll
        for (int t = 0; t < 4; t++) {
            uint32_t b0, b1, b2, b3;
            ldmat_x4_t(smem_u32(bbase + (k * 16) * 136 + t * 16), b0, b1, b2, b3);
            mma16816(C[2 * t], a0, a1, a2, a3, b0, b1);
            mma16816(C[2 * t + 1], a0, a1, a2, a3, b2, b3);
        }
    }
}

// -------- cp.async helpers --------
__device__ __forceinline__ void cpasync16(uint32_t saddr, const void* g) {
    asm volatile("cp.async.cg.shared.global [%0], [%1], 16;" :: "r"(saddr), "l"(g));
}
#define CP_COMMIT() asm volatile("cp.async.commit_group;" ::: "memory")
#define CP_WAIT0()  asm volatile("cp.async.wait_group 0;" ::: "memory")

// async copy pre-swizzled fp16 W image into smem — FULL 34816 B (2176 chunks)
__device__ __forceinline__ void copy_W_async(const __half* __restrict__ src,
                                             __half* __restrict__ Ws, int tid) {
    const char* s = (const char*)src;
    char* d = (char*)Ws;
    for (int i = tid; i < WS_HALFS / 8; i += 512) {
        cpasync16(smem_u32(d + i * 16), s + i * 16);
    }
}

// ===================== 3-layer HMMA GEMM: 128 nodes/block, 512 threads ======
// double-buffered W via cp.async; writes ONLY g_xwh (out handled by gcn gather)
__global__ __launch_bounds__(512, 2) void k_mlp_hmma(const float* __restrict__ b1,
                                                     const float* __restrict__ gamma,
                                                     const float* __restrict__ beta,
                                                     const float* __restrict__ rmean,
                                                     const float* __restrict__ rvar,
                                                     const float* __restrict__ b2) {
    extern __shared__ char smraw[];
    __half* WsA = (__half*)smraw;                            // 34816 B
    __half* WsB = (__half*)(smraw + WS_HALFS * 2);           // 34816 B
    __half* As  = (__half*)(smraw + WS_HALFS * 4);           // 34816 B
    float* scale_s = (float*)(smraw + WS_HALFS * 4 + AS_HALFS * 2);
    float* shift_s = scale_s + 128;
    float* b2s = shift_s + 128;

    int tid = threadIdx.x, lane = tid & 31, wid = tid >> 5;
    int node0 = blockIdx.x << 7;   // 128 nodes per block

    copy_W_async(g_w1h, WsA, tid);
    CP_COMMIT();
    if (tid < 128) {
        float sc = gamma[tid] * rsqrtf(rvar[tid] + 1e-5f);
        scale_s[tid] = sc;
        shift_s[tid] = (b1[tid] - rmean[tid]) * sc + beta[tid];
        b2s[tid] = b2[tid];
    }
    // load 128 aggr rows (fp16) coalesced
    for (int i = tid; i < 4096; i += 512) {
        int n = i >> 5, q = i & 31;
        int node = node0 + n;
        if (node > N_NODES - 1) node = N_NODES - 1;
        uint2 h = __ldg((const uint2*)(g_aggrh + (size_t)node * 128) + q);
        *(uint2*)(As + n * 136 + q * 4) = h;
    }
    CP_WAIT0();
    __syncthreads();

    int wm = wid & 7, wn = wid >> 3;   // 8 m-tiles x 2 n-halves
    int r0 = wm * 16 + (lane >> 2);
    float C[8][4];

    // prefetch W2 while phase-1 mma runs
    copy_W_async(g_w2h, WsB, tid);
    CP_COMMIT();

    // ---- phase 1: h1 = relu(BN(A @ W1)) ----
    mma_phase(As, WsA, wm, wn, lane, C);
    __syncthreads();
#pragma unroll
    for (int t = 0; t < 8; t++) {
        int c0 = wn * 64 + t * 8 + (lane & 3) * 2;
        float sc0 = scale_s[c0], sc1 = scale_s[c0 + 1];
        float sh0 = shift_s[c0], sh1 = shift_s[c0 + 1];
        *(__half2*)(As + r0 * 136 + c0) = __floats2half2_rn(
            fmaxf(C[t][0] * sc0 + sh0, 0.f), fmaxf(C[t][1] * sc1 + sh1, 0.f));
        *(__half2*)(As + (r0 + 8) * 136 + c0) = __floats2half2_rn(
            fmaxf(C[t][2] * sc0 + sh0, 0.f), fmaxf(C[t][3] * sc1 + sh1, 0.f));
    }
    CP_WAIT0();
    __syncthreads();

    // prefetch W3 (into WsA — all phase-1 reads of WsA finished at last barrier)
    copy_W_async(g_wch, WsA, tid);
    CP_COMMIT();

    // ---- phase 2: h2 = relu(A @ W2 + b2) ----
    mma_phase(As, WsB, wm, wn, lane, C);
    __syncthreads();
#pragma unroll
    for (int t = 0; t < 8; t++) {
        int c0 = wn * 64 + t * 8 + (lane & 3) * 2;
        float bb0 = b2s[c0], bb1 = b2s[c0 + 1];
        *(__half2*)(As + r0 * 136 + c0) = __floats2half2_rn(
            fmaxf(C[t][0] + bb0, 0.f), fmaxf(C[t][1] + bb1, 0.f));
        *(__half2*)(As + (r0 + 8) * 136 + c0) = __floats2half2_rn(
            fmaxf(C[t][2] + bb0, 0.f), fmaxf(C[t][3] + bb1, 0.f));
    }
    CP_WAIT0();
    __syncthreads();

    // ---- phase 3: xw = A @ [Wmu|Wls]; xwh = half(dinv*xw) ----
    mma_phase(As, WsA, wm, wn, lane, C);
    {
        int nodeA = node0 + r0;
        int nodeB = nodeA + 8;
        bool okA = nodeA < N_NODES, okB = nodeB < N_NODES;
        float dnA = okA ? g_dinv[nodeA] : 0.f;
        float dnB = okB ? g_dinv[nodeB] : 0.f;
#pragma unroll
        for (int t = 0; t < 8; t++) {
            int c0 = wn * 64 + t * 8 + (lane & 3) * 2;
            if (okA)
                *(__half2*)(g_xwh + (size_t)nodeA * 128 + c0) =
                    __floats2half2_rn(dnA * C[t][0], dnA * C[t][1]);
            if (okB)
                *(__half2*)(g_xwh + (size_t)nodeB * 128 + c0) =
                    __floats2half2_rn(dnB * C[t][2], dnB * C[t][3]);
        }
    }
}

// -------- GCN gather: out[n] = dinv[n]*(sum xwh[csr] + xwh[n]) + bias ------
__global__ __launch_bounds__(256) void k_gcn_gather(const float* __restrict__ bmu,
                                                    const float* __restrict__ bls,
                                                    float* __restrict__ out) {
    int n = blockIdx.x * 8 + (threadIdx.x >> 5);
    if (n >= N_NODES) return;
    int lane = threadIdx.x & 31;
    int beg = __ldg(g_off + n), end = __ldg(g_off + n + 1);
    const uint2* xh = (const uint2*)g_xwh;
    uint2 sh = __ldg(xh + (size_t)n * 32 + lane);  // self-loop term (dinv*xw)
    float2 accA = __half22float2(*(__half2*)&sh.x);
    float2 accB = __half22float2(*(__half2*)&sh.y);
    int j = beg;
    for (; j + 8 <= end; j += 8) {
        int idx[8];
#pragma unroll
        for (int t = 0; t < 8; t++) idx[t] = __ldg(g_csr + j + t);
        uint2 v[8];
#pragma unroll
        for (int t = 0; t < 8; t++) v[t] = __ldg(xh + (size_t)idx[t] * 32 + lane);
#pragma unroll
        for (int t = 0; t < 8; t++) {
            float2 f0 = __half22float2(*(__half2*)&v[t].x);
            float2 f1 = __half22float2(*(__half2*)&v[t].y);
            accA.x += f0.x; accA.y += f0.y;
            accB.x += f1.x; accB.y += f1.y;
        }
    }
    for (; j < end; j++) {
        int s = __ldg(g_csr + j);
        uint2 v = __ldg(xh + (size_t)s * 32 + lane);
        float2 f0 = __half22float2(*(__half2*)&v.x);
        float2 f1 = __half22float2(*(__half2*)&v.y);
        accA.x += f0.x; accA.y += f0.y;
        accB.x += f1.x; accB.y += f1.y;
    }
    float dn = g_dinv[n];
    int c0 = lane * 4;
    float4 bias = (c0 < 64) ? __ldg((const float4*)(bmu + c0))
                            : __ldg((const float4*)(bls + (c0 - 64)));
    float4 ov;
    ov.x = dn * accA.x + bias.x;
    ov.y = dn * accA.y + bias.y;
    ov.z = dn * accB.x + bias.z;
    ov.w = dn * accB.y + bias.w;
    float* ob = (c0 < 64) ? (out + (size_t)n * 64 + c0)
                          : (out + (size_t)N_NODES * 64 + (size_t)n * 64 + (c0 - 64));
    *(float4*)ob = ov;
}

extern "C" void kernel_launch(void* const* d_in, const int* in_sizes, int n_in,
                              void* d_out, int out_size) {
    const float* x     = (const float*)d_in[0];
    const void*  ei    = (const void*)d_in[1];
    const float* W1    = (const float*)d_in[2];
    const float* b1    = (const float*)d_in[3];
    const float* gamma = (const float*)d_in[4];
    const float* beta  = (const float*)d_in[5];
    const float* rmean = (const float*)d_in[6];
    const float* rvar  = (const float*)d_in[7];
    const float* W2    = (const float*)d_in[8];
    const float* b2    = (const float*)d_in[9];
    const float* Wmu   = (const float*)d_in[10];
    const float* bmu   = (const float*)d_in[11];
    const float* Wls   = (const float*)d_in[12];
    const float* bls   = (const float*)d_in[13];
    float* out = (float*)d_out;

    int E = in_sizes[1] / 2;

    const int SMEM = WS_HALFS * 2 * 2 + AS_HALFS * 2 + 384 * 4;  // 105984 B
    cudaFuncSetAttribute(k_mlp_hmma, cudaFuncAttributeMaxDynamicSharedMemorySize, SMEM);

    int eb = (E + 255) / 256;
    int nb = (N_NODES + 7) / 8;
    int mb = (N_NODES + 127) / 128;

    k_count<<<eb, 256>>>(ei, x, W1, W2, Wmu, Wls, E);                  // 0
    k_scan<<<1, 1024>>>();                                             // 1
    k_fill<<<eb, 256>>>(E);                                            // 2
    k_gin_gather<<<nb, 256>>>();                                       // 3 <- profiled
    k_mlp_hmma<<<mb, 512, SMEM>>>(b1, gamma, beta, rmean, rvar, b2);   // 4
    k_gcn_gather<<<nb, 256>>>(bmu, bls, out);                          // 5
}

// round 14
// speedup vs baseline: 4.1506x; 1.0710x over previous
#include <cuda_runtime.h>
#include <cuda_fp16.h>
#include <cstdint>

#define N_NODES 100000
#define DIMH 128
#define E_CAP 4000000
#define WS_HALFS (128 * 136)
#define AS_HALFS (128 * 136)

// -------- scratch (device globals; no allocation allowed) --------
__device__ __align__(16) __half g_xh[(size_t)N_NODES * DIMH];    // fp16 copy of x
__device__ __align__(16) __half g_aggrh[(size_t)N_NODES * DIMH]; // fp16 x+sum(neigh)
__device__ __align__(16) __half g_xwh[(size_t)N_NODES * DIMH];   // fp16 dinv-scaled xw
__device__ __align__(16) __half g_w1h[WS_HALFS];  // pre-swizzled fp16 W1
__device__ __align__(16) __half g_w2h[WS_HALFS];  // pre-swizzled fp16 W2
__device__ __align__(16) __half g_wch[WS_HALFS];  // pre-swizzled fp16 [Wmu|Wls]
__device__ float g_dinv[N_NODES];
__device__ int   g_deg[N_NODES];   // zero at load; k_fill re-zeros each call
__device__ int   g_off[N_NODES + 1];
__device__ int   g_cur[N_NODES];
__device__ int   g_csr[E_CAP];
__device__ int   g_done;           // ticket for last-block scan; reset each call

// ==== count + conversions + (last block) scan, all in one launch ====
__global__ __launch_bounds__(1024) void k_count_scan(const void* __restrict__ ei,
                                                     const float* __restrict__ x,
                                                     const float* __restrict__ W1,
                                                     const float* __restrict__ W2,
                                                     const float* __restrict__ Wmu,
                                                     const float* __restrict__ Wls,
                                                     int E) {
    __shared__ int s_is64;
    __shared__ int s_last;
    if (threadIdx.x < 32) {
        unsigned w = __ldg((const unsigned*)ei + threadIdx.x * 2 + 1);
        unsigned b = __ballot_sync(0xffffffffu, w != 0u);
        if (threadIdx.x == 0) s_is64 = (b == 0u);
    }
    __syncthreads();
    int gid = blockIdx.x * 1024 + threadIdx.x;
    int total = gridDim.x * 1024;
    if (gid < E) {
        int d;
        if (s_is64) d = (int)__ldg((const long long*)ei + E + gid);
        else        d = __ldg((const int*)ei + E + gid);
        atomicAdd(&g_deg[d], 1);
    }
    // x (fp32) -> g_xh (fp16)
    const float2* x2 = (const float2*)x;
    __half2* xh2 = (__half2*)g_xh;
    const int NH2 = N_NODES * (DIMH / 2);
    for (int i = gid; i < NH2; i += total) {
        float2 v = __ldg(x2 + i);
        xh2[i] = __floats2half2_rn(v.x, v.y);
    }
    // weights -> fp16 smem-image layout (row k at k*136, float4 chunk c4 at c4*4)
    for (int i = gid; i < 3 * 4096; i += total) {
        int w = i >> 12, j = i & 4095;
        int k = j >> 5, c4 = j & 31;
        float4 v;
        __half* dst;
        if (w == 0)      { v = __ldg((const float4*)W1 + j); dst = g_w1h; }
        else if (w == 1) { v = __ldg((const float4*)W2 + j); dst = g_w2h; }
        else {
            v = (c4 < 16) ? __ldg((const float4*)Wmu + k * 16 + c4)
                          : __ldg((const float4*)Wls + k * 16 + (c4 - 16));
            dst = g_wch;
        }
        uint2 h;
        *(__half2*)&h.x = __floats2half2_rn(v.x, v.y);
        *(__half2*)&h.y = __floats2half2_rn(v.z, v.w);
        *(uint2*)(dst + k * 136 + c4 * 4) = h;
    }

    // ---- ticket: last block to finish runs the scan ----
    __threadfence();
    __syncthreads();
    if (threadIdx.x == 0)
        s_last = (atomicAdd(&g_done, 1) == (int)gridDim.x - 1);
    __syncthreads();
    if (!s_last) return;
    if (threadIdx.x == 0) g_done = 0;  // reset for next graph replay

    // ---- inline coalesced tiled scan over g_deg (1024 threads) ----
    __shared__ int wsum[32];
    __shared__ int s_carry;
    int tid = threadIdx.x, lane = tid & 31, wid = tid >> 5;
    if (tid == 0) s_carry = 0;
    __syncthreads();
    const int NT = (N_NODES + 1023) / 1024;  // 98
    int dg_next = (tid < N_NODES) ? g_deg[tid] : 0;
    for (int t = 0; t < NT; t++) {
        int idx = t * 1024 + tid;
        int dg = dg_next;
        int nidx = idx + 1024;
        if (t + 1 < NT) dg_next = (nidx < N_NODES) ? g_deg[nidx] : 0;  // prefetch
        int v = dg;
#pragma unroll
        for (int o = 1; o < 32; o <<= 1) {
            int u = __shfl_up_sync(~0u, v, o);
            if (lane >= o) v += u;
        }
        if (lane == 31) wsum[wid] = v;
        __syncthreads();
        if (wid == 0) {
            int w = wsum[lane];
#pragma unroll
            for (int o = 1; o < 32; o <<= 1) {
                int u = __shfl_up_sync(~0u, w, o);
                if (lane >= o) w += u;
            }
            wsum[lane] = w;
        }
        __syncthreads();
        int excl = v - dg + ((wid > 0) ? wsum[wid - 1] : 0) + s_carry;
        if (idx < N_NODES) {
            g_off[idx] = excl;
            g_cur[idx] = excl;
            g_dinv[idx] = rsqrtf((float)dg + 1.0f);
        }
        __syncthreads();
        if (tid == 0) s_carry += wsum[31];
        __syncthreads();
    }
    if (tid == 0) g_off[N_NODES] = s_carry;
}

// -------- fill CSR (reads ei directly); re-zero g_deg for next call --------
__global__ __launch_bounds__(256) void k_fill(const void* __restrict__ ei, int E) {
    __shared__ int s_is64;
    if (threadIdx.x < 32) {
        unsigned w = __ldg((const unsigned*)ei + threadIdx.x * 2 + 1);
        unsigned b = __ballot_sync(0xffffffffu, w != 0u);
        if (threadIdx.x == 0) s_is64 = (b == 0u);
    }
    __syncthreads();
    int e = blockIdx.x * 256 + threadIdx.x;
    int total = gridDim.x * 256;
    if (e < E) {
        int s, d;
        if (s_is64) {
            s = (int)__ldg((const long long*)ei + e);
            d = (int)__ldg((const long long*)ei + E + e);
        } else {
            s = __ldg((const int*)ei + e);
            d = __ldg((const int*)ei + E + e);
        }
        int pos = atomicAdd(&g_cur[d], 1);
        g_csr[pos] = s;
    }
    for (int i = e; i < N_NODES; i += total) g_deg[i] = 0;
}

// -------- GIN gather (fp16): aggrh[n] = half(xh[n] + sum xh[csr]) ----------
__global__ __launch_bounds__(256) void k_gin_gather() {
    int n = blockIdx.x * 8 + (threadIdx.x >> 5);
    if (n >= N_NODES) return;
    int lane = threadIdx.x & 31;
    int beg = __ldg(g_off + n), end = __ldg(g_off + n + 1);
    const uint2* xh = (const uint2*)g_xh;
    uint2 sh = __ldg(xh + (size_t)n * 32 + lane);  // self term (fp16)
    float2 accA = __half22float2(*(__half2*)&sh.x);
    float2 accB = __half22float2(*(__half2*)&sh.y);
    int j = beg;
    for (; j + 8 <= end; j += 8) {
        int idx[8];
#pragma unroll
        for (int t = 0; t < 8; t++) idx[t] = __ldg(g_csr + j + t);
        uint2 v[8];
#pragma unroll
        for (int t = 0; t < 8; t++) v[t] = __ldg(xh + (size_t)idx[t] * 32 + lane);
#pragma unroll
        for (int t = 0; t < 8; t++) {
            float2 f0 = __half22float2(*(__half2*)&v[t].x);
            float2 f1 = __half22float2(*(__half2*)&v[t].y);
            accA.x += f0.x; accA.y += f0.y;
            accB.x += f1.x; accB.y += f1.y;
        }
    }
    for (; j < end; j++) {
        int s = __ldg(g_csr + j);
        uint2 v = __ldg(xh + (size_t)s * 32 + lane);
        float2 f0 = __half22float2(*(__half2*)&v.x);
        float2 f1 = __half22float2(*(__half2*)&v.y);
        accA.x += f0.x; accA.y += f0.y;
        accB.x += f1.x; accB.y += f1.y;
    }
    uint2 hx;
    *(__half2*)&hx.x = __floats2half2_rn(accA.x, accA.y);
    *(__half2*)&hx.y = __floats2half2_rn(accB.x, accB.y);
    *(uint2*)(g_aggrh + (size_t)n * 128 + lane * 4) = hx;
}

// ===================== HMMA plumbing =====================
__device__ __forceinline__ uint32_t smem_u32(const void* p) {
    return (uint32_t)__cvta_generic_to_shared(p);
}
__device__ __forceinline__ void ldmat_x4(uint32_t addr, uint32_t& r0, uint32_t& r1,
                                         uint32_t& r2, uint32_t& r3) {
    asm volatile("ldmatrix.sync.aligned.m8n8.x4.shared.b16 {%0,%1,%2,%3}, [%4];"
                 : "=r"(r0), "=r"(r1), "=r"(r2), "=r"(r3) : "r"(addr));
}
__device__ __forceinline__ void ldmat_x4_t(uint32_t addr, uint32_t& r0, uint32_t& r1,
                                           uint32_t& r2, uint32_t& r3) {
    asm volatile("ldmatrix.sync.aligned.m8n8.x4.trans.shared.b16 {%0,%1,%2,%3}, [%4];"
                 : "=r"(r0), "=r"(r1), "=r"(r2), "=r"(r3) : "r"(addr));
}
__device__ __forceinline__ void mma16816(float* c, uint32_t a0, uint32_t a1, uint32_t a2,
                                         uint32_t a3, uint32_t b0, uint32_t b1) {
    asm volatile(
        "mma.sync.aligned.m16n8k16.row.col.f32.f16.f16.f32 "
        "{%0,%1,%2,%3}, {%4,%5,%6,%7}, {%8,%9}, {%0,%1,%2,%3};"
        : "+f"(c[0]), "+f"(c[1]), "+f"(c[2]), "+f"(c[3])
        : "r"(a0), "r"(a1), "r"(a2), "r"(a3), "r"(b0), "r"(b1));
}

// one GEMM phase: C[8][4] += As[wm*16.., :] @ Ws[:, wn*64..]
__device__ __forceinline__ void mma_phase(const __half* As, const __half* Ws,
                                          int wm, int wn, int lane, float C[8][4]) {
#pragma unroll
    for (int t = 0; t < 8; t++) {
        C[t][0] = 0.f; C[t][1] = 0.f; C[t][2] = 0.f; C[t][3] = 0.f;
    }
    int l15 = lane & 15, l16 = lane >> 4;
    const __half* abase = As + (wm * 16 + l15) * 136 + l16 * 8;
    const __half* bbase = Ws + l15 * 136 + wn * 64 + l16 * 8;
#pragma unroll
    for (int k = 0; k < 8; k++) {
        uint32_t a0, a1, a2, a3;
        ldmat_x4(smem_u32(abase + k * 16), a0, a1, a2, a3);
#pragma unroll
        for (int t = 0; t < 4; t++) {
            uint32_t b0, b1, b2, b3;
            ldmat_x4_t(smem_u32(bbase + (k * 16) * 136 + t * 16), b0, b1, b2, b3);
            mma16816(C[2 * t], a0, a1, a2, a3, b0, b1);
            mma16816(C[2 * t + 1], a0, a1, a2, a3, b2, b3);
        }
    }
}

// -------- cp.async helpers --------
__device__ __forceinline__ void cpasync16(uint32_t saddr, const void* g) {
    asm volatile("cp.async.cg.shared.global [%0], [%1], 16;" :: "r"(saddr), "l"(g));
}
#define CP_COMMIT() asm volatile("cp.async.commit_group;" ::: "memory")
#define CP_WAIT0()  asm volatile("cp.async.wait_group 0;" ::: "memory")

// async copy pre-swizzled fp16 W image into smem — FULL 34816 B (2176 chunks)
__device__ __forceinline__ void copy_W_async(const __half* __restrict__ src,
                                             __half* __restrict__ Ws, int tid) {
    const char* s = (const char*)src;
    char* d = (char*)Ws;
    for (int i = tid; i < WS_HALFS / 8; i += 512) {
        cpasync16(smem_u32(d + i * 16), s + i * 16);
    }
}

// ===================== 3-layer HMMA GEMM: 128 nodes/block, 512 threads ======
__global__ __launch_bounds__(512, 2) void k_mlp_hmma(const float* __restrict__ b1,
                                                     const float* __restrict__ gamma,
                                                     const float* __restrict__ beta,
                                                     const float* __restrict__ rmean,
                                                     const float* __restrict__ rvar,
                                                     const float* __restrict__ b2) {
    extern __shared__ char smraw[];
    __half* WsA = (__half*)smraw;                            // 34816 B
    __half* WsB = (__half*)(smraw + WS_HALFS * 2);           // 34816 B
    __half* As  = (__half*)(smraw + WS_HALFS * 4);           // 34816 B
    float* scale_s = (float*)(smraw + WS_HALFS * 4 + AS_HALFS * 2);
    float* shift_s = scale_s + 128;
    float* b2s = shift_s + 128;

    int tid = threadIdx.x, lane = tid & 31, wid = tid >> 5;
    int node0 = blockIdx.x << 7;   // 128 nodes per block

    copy_W_async(g_w1h, WsA, tid);
    CP_COMMIT();
    if (tid < 128) {
        float sc = gamma[tid] * rsqrtf(rvar[tid] + 1e-5f);
        scale_s[tid] = sc;
        shift_s[tid] = (b1[tid] - rmean[tid]) * sc + beta[tid];
        b2s[tid] = b2[tid];
    }
    // load 128 aggr rows (fp16) coalesced
    for (int i = tid; i < 4096; i += 512) {
        int n = i >> 5, q = i & 31;
        int node = node0 + n;
        if (node > N_NODES - 1) node = N_NODES - 1;
        uint2 h = __ldg((const uint2*)(g_aggrh + (size_t)node * 128) + q);
        *(uint2*)(As + n * 136 + q * 4) = h;
    }
    CP_WAIT0();
    __syncthreads();

    int wm = wid & 7, wn = wid >> 3;   // 8 m-tiles x 2 n-halves
    int r0 = wm * 16 + (lane >> 2);
    float C[8][4];

    // prefetch W2 while phase-1 mma runs
    copy_W_async(g_w2h, WsB, tid);
    CP_COMMIT();

    // ---- phase 1: h1 = relu(BN(A @ W1)) ----
    mma_phase(As, WsA, wm, wn, lane, C);
    __syncthreads();
#pragma unroll
    for (int t = 0; t < 8; t++) {
        int c0 = wn * 64 + t * 8 + (lane & 3) * 2;
        float sc0 = scale_s[c0], sc1 = scale_s[c0 + 1];
        float sh0 = shift_s[c0], sh1 = shift_s[c0 + 1];
        *(__half2*)(As + r0 * 136 + c0) = __floats2half2_rn(
            fmaxf(C[t][0] * sc0 + sh0, 0.f), fmaxf(C[t][1] * sc1 + sh1, 0.f));
        *(__half2*)(As + (r0 + 8) * 136 + c0) = __floats2half2_rn(
            fmaxf(C[t][2] * sc0 + sh0, 0.f), fmaxf(C[t][3] * sc1 + sh1, 0.f));
    }
    CP_WAIT0();
    __syncthreads();

    // prefetch W3 (into WsA — all phase-1 reads of WsA finished at last barrier)
    copy_W_async(g_wch, WsA, tid);
    CP_COMMIT();

    // ---- phase 2: h2 = relu(A @ W2 + b2) ----
    mma_phase(As, WsB, wm, wn, lane, C);
    __syncthreads();
#pragma unroll
    for (int t = 0; t < 8; t++) {
        int c0 = wn * 64 + t * 8 + (lane & 3) * 2;
        float bb0 = b2s[c0], bb1 = b2s[c0 + 1];
        *(__half2*)(As + r0 * 136 + c0) = __floats2half2_rn(
            fmaxf(C[t][0] + bb0, 0.f), fmaxf(C[t][1] + bb1, 0.f));
        *(__half2*)(As + (r0 + 8) * 136 + c0) = __floats2half2_rn(
            fmaxf(C[t][2] + bb0, 0.f), fmaxf(C[t][3] + bb1, 0.f));
    }
    CP_WAIT0();
    __syncthreads();

    // ---- phase 3: xw = A @ [Wmu|Wls]; xwh = half(dinv*xw) ----
    mma_phase(As, WsA, wm, wn, lane, C);
    {
        int nodeA = node0 + r0;
        int nodeB = nodeA + 8;
        bool okA = nodeA < N_NODES, okB = nodeB < N_NODES;
        float dnA = okA ? g_dinv[nodeA] : 0.f;
        float dnB = okB ? g_dinv[nodeB] : 0.f;
#pragma unroll
        for (int t = 0; t < 8; t++) {
            int c0 = wn * 64 + t * 8 + (lane & 3) * 2;
            if (okA)
                *(__half2*)(g_xwh + (size_t)nodeA * 128 + c0) =
                    __floats2half2_rn(dnA * C[t][0], dnA * C[t][1]);
            if (okB)
                *(__half2*)(g_xwh + (size_t)nodeB * 128 + c0) =
                    __floats2half2_rn(dnB * C[t][2], dnB * C[t][3]);
        }
    }
}

// -------- GCN gather: out[n] = dinv[n]*(sum xwh[csr] + xwh[n]) + bias ------
__global__ __launch_bounds__(256) void k_gcn_gather(const float* __restrict__ bmu,
                                                    const float* __restrict__ bls,
                                                    float* __restrict__ out) {
    int n = blockIdx.x * 8 + (threadIdx.x >> 5);
    if (n >= N_NODES) return;
    int lane = threadIdx.x & 31;
    int beg = __ldg(g_off + n), end = __ldg(g_off + n + 1);
    const uint2* xh = (const uint2*)g_xwh;
    uint2 sh = __ldg(xh + (size_t)n * 32 + lane);  // self-loop term (dinv*xw)
    float2 accA = __half22float2(*(__half2*)&sh.x);
    float2 accB = __half22float2(*(__half2*)&sh.y);
    int j = beg;
    for (; j + 8 <= end; j += 8) {
        int idx[8];
#pragma unroll
        for (int t = 0; t < 8; t++) idx[t] = __ldg(g_csr + j + t);
        uint2 v[8];
#pragma unroll
        for (int t = 0; t < 8; t++) v[t] = __ldg(xh + (size_t)idx[t] * 32 + lane);
#pragma unroll
        for (int t = 0; t < 8; t++) {
            float2 f0 = __half22float2(*(__half2*)&v[t].x);
            float2 f1 = __half22float2(*(__half2*)&v[t].y);
            accA.x += f0.x; accA.y += f0.y;
            accB.x += f1.x; accB.y += f1.y;
        }
    }
    for (; j < end; j++) {
        int s = __ldg(g_csr + j);
        uint2 v = __ldg(xh + (size_t)s * 32 + lane);
        float2 f0 = __half22float2(*(__half2*)&v.x);
        float2 f1 = __half22float2(*(__half2*)&v.y);
        accA.x += f0.x; accA.y += f0.y;
        accB.x += f1.x; accB.y += f1.y;
    }
    float dn = g_dinv[n];
    int c0 = lane * 4;
    float4 bias = (c0 < 64) ? __ldg((const float4*)(bmu + c0))
                            : __ldg((const float4*)(bls + (c0 - 64)));
    float4 ov;
    ov.x = dn * accA.x + bias.x;
    ov.y = dn * accA.y + bias.y;
    ov.z = dn * accB.x + bias.z;
    ov.w = dn * accB.y + bias.w;
    float* ob = (c0 < 64) ? (out + (size_t)n * 64 + c0)
                          : (out + (size_t)N_NODES * 64 + (size_t)n * 64 + (c0 - 64));
    *(float4*)ob = ov;
}

extern "C" void kernel_launch(void* const* d_in, const int* in_sizes, int n_in,
                              void* d_out, int out_size) {
    const float* x     = (const float*)d_in[0];
    const void*  ei    = (const void*)d_in[1];
    const float* W1    = (const float*)d_in[2];
    const float* b1    = (const float*)d_in[3];
    const float* gamma = (const float*)d_in[4];
    const float* beta  = (const float*)d_in[5];
    const float* rmean = (const float*)d_in[6];
    const float* rvar  = (const float*)d_in[7];
    const float* W2    = (const float*)d_in[8];
    const float* b2    = (const float*)d_in[9];
    const float* Wmu   = (const float*)d_in[10];
    const float* bmu   = (const float*)d_in[11];
    const float* Wls   = (const float*)d_in[12];
    const float* bls   = (const float*)d_in[13];
    float* out = (float*)d_out;

    int E = in_sizes[1] / 2;

    const int SMEM = WS_HALFS * 2 * 2 + AS_HALFS * 2 + 384 * 4;  // 105984 B
    cudaFuncSetAttribute(k_mlp_hmma, cudaFuncAttributeMaxDynamicSharedMemorySize, SMEM);

    int cb = (E + 1023) / 1024;
    int eb = (E + 255) / 256;
    int nb = (N_NODES + 7) / 8;
    int mb = (N_NODES + 127) / 128;

    k_count_scan<<<cb, 1024>>>(ei, x, W1, W2, Wmu, Wls, E);            // 0
    k_fill<<<eb, 256>>>(ei, E);                                        // 1
    k_gin_gather<<<nb, 256>>>();                                       // 2
    k_mlp_hmma<<<mb, 512, SMEM>>>(b1, gamma, beta, rmean, rvar, b2);   // 3 <- profiled
    k_gcn_gather<<<nb, 256>>>(bmu, bls, out);                          // 4
}

// round 15
// speedup vs baseline: 4.2265x; 1.0183x over previous
#include <cuda_runtime.h>
#include <cuda_fp16.h>
#include <cstdint>

#define N_NODES 100000
#define DIMH 128
#define E_CAP 4000000
#define WS_HALFS (128 * 136)
#define AS_HALFS (128 * 136)

// -------- scratch (device globals; no allocation allowed) --------
__device__ __align__(16) __half g_xh[(size_t)N_NODES * DIMH];    // fp16 copy of x
__device__ __align__(16) __half g_aggrh[(size_t)N_NODES * DIMH]; // fp16 x+sum(neigh)
__device__ __align__(16) __half g_xwh[(size_t)N_NODES * DIMH];   // fp16 dinv-scaled xw
__device__ __align__(16) __half g_w1h[WS_HALFS];  // pre-swizzled fp16 W1
__device__ __align__(16) __half g_w2h[WS_HALFS];  // pre-swizzled fp16 W2
__device__ __align__(16) __half g_wch[WS_HALFS];  // pre-swizzled fp16 [Wmu|Wls]
__device__ float g_dinv[N_NODES];
__device__ int   g_deg[N_NODES];   // zero at load; k_fill re-zeros each call
__device__ int   g_off[N_NODES + 1];
__device__ int   g_cur[N_NODES];
__device__ int   g_csr[E_CAP];
__device__ int   g_done;           // ticket for last-block scan; reset each call

// ==== count + conversions + (last block) scan, all in one launch ====
__global__ __launch_bounds__(1024) void k_count_scan(const void* __restrict__ ei,
                                                     const float* __restrict__ x,
                                                     const float* __restrict__ W1,
                                                     const float* __restrict__ W2,
                                                     const float* __restrict__ Wmu,
                                                     const float* __restrict__ Wls,
                                                     int E) {
    __shared__ int s_is64;
    __shared__ int s_last;
    if (threadIdx.x < 32) {
        unsigned w = __ldg((const unsigned*)ei + threadIdx.x * 2 + 1);
        unsigned b = __ballot_sync(0xffffffffu, w != 0u);
        if (threadIdx.x == 0) s_is64 = (b == 0u);
    }
    __syncthreads();
    int gid = blockIdx.x * 1024 + threadIdx.x;
    int total = gridDim.x * 1024;
    if (gid < E) {
        int d;
        if (s_is64) d = (int)__ldg((const long long*)ei + E + gid);
        else        d = __ldg((const int*)ei + E + gid);
        atomicAdd(&g_deg[d], 1);
    }
    // x (fp32) -> g_xh (fp16)
    const float2* x2 = (const float2*)x;
    __half2* xh2 = (__half2*)g_xh;
    const int NH2 = N_NODES * (DIMH / 2);
    for (int i = gid; i < NH2; i += total) {
        float2 v = __ldg(x2 + i);
        xh2[i] = __floats2half2_rn(v.x, v.y);
    }
    // weights -> fp16 smem-image layout (row k at k*136, float4 chunk c4 at c4*4)
    for (int i = gid; i < 3 * 4096; i += total) {
        int w = i >> 12, j = i & 4095;
        int k = j >> 5, c4 = j & 31;
        float4 v;
        __half* dst;
        if (w == 0)      { v = __ldg((const float4*)W1 + j); dst = g_w1h; }
        else if (w == 1) { v = __ldg((const float4*)W2 + j); dst = g_w2h; }
        else {
            v = (c4 < 16) ? __ldg((const float4*)Wmu + k * 16 + c4)
                          : __ldg((const float4*)Wls + k * 16 + (c4 - 16));
            dst = g_wch;
        }
        uint2 h;
        *(__half2*)&h.x = __floats2half2_rn(v.x, v.y);
        *(__half2*)&h.y = __floats2half2_rn(v.z, v.w);
        *(uint2*)(dst + k * 136 + c4 * 4) = h;
    }

    // ---- ticket: last block to finish runs the scan ----
    __threadfence();
    __syncthreads();
    if (threadIdx.x == 0)
        s_last = (atomicAdd(&g_done, 1) == (int)gridDim.x - 1);
    __syncthreads();
    if (!s_last) return;
    if (threadIdx.x == 0) g_done = 0;  // reset for next graph replay

    // ---- inline coalesced tiled scan over g_deg (1024 threads) ----
    __shared__ int wsum[32];
    __shared__ int s_carry;
    int tid = threadIdx.x, lane = tid & 31, wid = tid >> 5;
    if (tid == 0) s_carry = 0;
    __syncthreads();
    const int NT = (N_NODES + 1023) / 1024;  // 98
    int dg_next = (tid < N_NODES) ? g_deg[tid] : 0;
    for (int t = 0; t < NT; t++) {
        int idx = t * 1024 + tid;
        int dg = dg_next;
        int nidx = idx + 1024;
        if (t + 1 < NT) dg_next = (nidx < N_NODES) ? g_deg[nidx] : 0;  // prefetch
        int v = dg;
#pragma unroll
        for (int o = 1; o < 32; o <<= 1) {
            int u = __shfl_up_sync(~0u, v, o);
            if (lane >= o) v += u;
        }
        if (lane == 31) wsum[wid] = v;
        __syncthreads();
        if (wid == 0) {
            int w = wsum[lane];
#pragma unroll
            for (int o = 1; o < 32; o <<= 1) {
                int u = __shfl_up_sync(~0u, w, o);
                if (lane >= o) w += u;
            }
            wsum[lane] = w;
        }
        __syncthreads();
        int excl = v - dg + ((wid > 0) ? wsum[wid - 1] : 0) + s_carry;
        if (idx < N_NODES) {
            g_off[idx] = excl;
            g_cur[idx] = excl;
            g_dinv[idx] = rsqrtf((float)dg + 1.0f);
        }
        __syncthreads();
        if (tid == 0) s_carry += wsum[31];
        __syncthreads();
    }
    if (tid == 0) g_off[N_NODES] = s_carry;
}

// -------- fill CSR (reads ei directly); re-zero g_deg for next call --------
__global__ __launch_bounds__(256) void k_fill(const void* __restrict__ ei, int E) {
    __shared__ int s_is64;
    if (threadIdx.x < 32) {
        unsigned w = __ldg((const unsigned*)ei + threadIdx.x * 2 + 1);
        unsigned b = __ballot_sync(0xffffffffu, w != 0u);
        if (threadIdx.x == 0) s_is64 = (b == 0u);
    }
    __syncthreads();
    int e = blockIdx.x * 256 + threadIdx.x;
    int total = gridDim.x * 256;
    if (e < E) {
        int s, d;
        if (s_is64) {
            s = (int)__ldg((const long long*)ei + e);
            d = (int)__ldg((const long long*)ei + E + e);
        } else {
            s = __ldg((const int*)ei + e);
            d = __ldg((const int*)ei + E + e);
        }
        int pos = atomicAdd(&g_cur[d], 1);
        g_csr[pos] = s;
    }
    for (int i = e; i < N_NODES; i += total) g_deg[i] = 0;
}

// -------- GIN gather (fp16): aggrh[n] = half(xh[n] + sum xh[csr]) ----------
__global__ __launch_bounds__(256) void k_gin_gather() {
    int n = blockIdx.x * 8 + (threadIdx.x >> 5);
    if (n >= N_NODES) return;
    int lane = threadIdx.x & 31;
    int beg = __ldg(g_off + n), end = __ldg(g_off + n + 1);
    const uint2* xh = (const uint2*)g_xh;
    uint2 sh = __ldg(xh + (size_t)n * 32 + lane);  // self term (fp16)
    float2 accA = __half22float2(*(__half2*)&sh.x);
    float2 accB = __half22float2(*(__half2*)&sh.y);
    int j = beg;
    for (; j + 8 <= end; j += 8) {
        int idx[8];
#pragma unroll
        for (int t = 0; t < 8; t++) idx[t] = __ldg(g_csr + j + t);
        uint2 v[8];
#pragma unroll
        for (int t = 0; t < 8; t++) v[t] = __ldg(xh + (size_t)idx[t] * 32 + lane);
#pragma unroll
        for (int t = 0; t < 8; t++) {
            float2 f0 = __half22float2(*(__half2*)&v[t].x);
            float2 f1 = __half22float2(*(__half2*)&v[t].y);
            accA.x += f0.x; accA.y += f0.y;
            accB.x += f1.x; accB.y += f1.y;
        }
    }
    for (; j < end; j++) {
        int s = __ldg(g_csr + j);
        uint2 v = __ldg(xh + (size_t)s * 32 + lane);
        float2 f0 = __half22float2(*(__half2*)&v.x);
        float2 f1 = __half22float2(*(__half2*)&v.y);
        accA.x += f0.x; accA.y += f0.y;
        accB.x += f1.x; accB.y += f1.y;
    }
    uint2 hx;
    *(__half2*)&hx.x = __floats2half2_rn(accA.x, accA.y);
    *(__half2*)&hx.y = __floats2half2_rn(accB.x, accB.y);
    *(uint2*)(g_aggrh + (size_t)n * 128 + lane * 4) = hx;
}

// ===================== HMMA plumbing =====================
__device__ __forceinline__ uint32_t smem_u32(const void* p) {
    return (uint32_t)__cvta_generic_to_shared(p);
}
__device__ __forceinline__ void ldmat_x4(uint32_t addr, uint32_t& r0, uint32_t& r1,
                                         uint32_t& r2, uint32_t& r3) {
    asm volatile("ldmatrix.sync.aligned.m8n8.x4.shared.b16 {%0,%1,%2,%3}, [%4];"
                 : "=r"(r0), "=r"(r1), "=r"(r2), "=r"(r3) : "r"(addr));
}
__device__ __forceinline__ void ldmat_x4_t(uint32_t addr, uint32_t& r0, uint32_t& r1,
                                           uint32_t& r2, uint32_t& r3) {
    asm volatile("ldmatrix.sync.aligned.m8n8.x4.trans.shared.b16 {%0,%1,%2,%3}, [%4];"
                 : "=r"(r0), "=r"(r1), "=r"(r2), "=r"(r3) : "r"(addr));
}
__device__ __forceinline__ void mma16816(float* c, uint32_t a0, uint32_t a1, uint32_t a2,
                                         uint32_t a3, uint32_t b0, uint32_t b1) {
    asm volatile(
        "mma.sync.aligned.m16n8k16.row.col.f32.f16.f16.f32 "
        "{%0,%1,%2,%3}, {%4,%5,%6,%7}, {%8,%9}, {%0,%1,%2,%3};"
        : "+f"(c[0]), "+f"(c[1]), "+f"(c[2]), "+f"(c[3])
        : "r"(a0), "r"(a1), "r"(a2), "r"(a3), "r"(b0), "r"(b1));
}

// one GEMM phase, 4x4 warp tile: warp owns rows wm*32..+31, cols wn*32..+31
// C[mi*4+nt][4]: mi=m-tile (16 rows), nt=n-tile (8 cols)
__device__ __forceinline__ void mma_phase(const __half* As, const __half* Ws,
                                          int wm, int wn, int lane, float C[8][4]) {
#pragma unroll
    for (int t = 0; t < 8; t++) {
        C[t][0] = 0.f; C[t][1] = 0.f; C[t][2] = 0.f; C[t][3] = 0.f;
    }
    int l15 = lane & 15, l16 = lane >> 4;
    const __half* a0 = As + (wm * 32 + l15) * 136 + l16 * 8;
    const __half* a1 = a0 + 16 * 136;
    const __half* bb = Ws + l15 * 136 + wn * 32 + l16 * 8;
#pragma unroll
    for (int k = 0; k < 8; k++) {
        uint32_t A0[4], A1[4];
        ldmat_x4(smem_u32(a0 + k * 16), A0[0], A0[1], A0[2], A0[3]);
        ldmat_x4(smem_u32(a1 + k * 16), A1[0], A1[1], A1[2], A1[3]);
        uint32_t b0, b1, b2, b3, b4, b5, b6, b7;
        ldmat_x4_t(smem_u32(bb + (k * 16) * 136), b0, b1, b2, b3);
        ldmat_x4_t(smem_u32(bb + (k * 16) * 136 + 16), b4, b5, b6, b7);
        mma16816(C[0], A0[0], A0[1], A0[2], A0[3], b0, b1);
        mma16816(C[1], A0[0], A0[1], A0[2], A0[3], b2, b3);
        mma16816(C[2], A0[0], A0[1], A0[2], A0[3], b4, b5);
        mma16816(C[3], A0[0], A0[1], A0[2], A0[3], b6, b7);
        mma16816(C[4], A1[0], A1[1], A1[2], A1[3], b0, b1);
        mma16816(C[5], A1[0], A1[1], A1[2], A1[3], b2, b3);
        mma16816(C[6], A1[0], A1[1], A1[2], A1[3], b4, b5);
        mma16816(C[7], A1[0], A1[1], A1[2], A1[3], b6, b7);
    }
}

// -------- cp.async helpers --------
__device__ __forceinline__ void cpasync16(uint32_t saddr, const void* g) {
    asm volatile("cp.async.cg.shared.global [%0], [%1], 16;" :: "r"(saddr), "l"(g));
}
#define CP_COMMIT() asm volatile("cp.async.commit_group;" ::: "memory")
#define CP_WAIT0()  asm volatile("cp.async.wait_group 0;" ::: "memory")

// async copy pre-swizzled fp16 W image into smem — FULL 34816 B (2176 chunks)
__device__ __forceinline__ void copy_W_async(const __half* __restrict__ src,
                                             __half* __restrict__ Ws, int tid) {
    const char* s = (const char*)src;
    char* d = (char*)Ws;
    for (int i = tid; i < WS_HALFS / 8; i += 512) {
        cpasync16(smem_u32(d + i * 16), s + i * 16);
    }
}

// ===================== 3-layer HMMA GEMM: 128 nodes/block, 512 threads ======
__global__ __launch_bounds__(512, 2) void k_mlp_hmma(const float* __restrict__ b1,
                                                     const float* __restrict__ gamma,
                                                     const float* __restrict__ beta,
                                                     const float* __restrict__ rmean,
                                                     const float* __restrict__ rvar,
                                                     const float* __restrict__ b2) {
    extern __shared__ char smraw[];
    __half* WsA = (__half*)smraw;                            // 34816 B
    __half* WsB = (__half*)(smraw + WS_HALFS * 2);           // 34816 B
    __half* As  = (__half*)(smraw + WS_HALFS * 4);           // 34816 B
    float* scale_s = (float*)(smraw + WS_HALFS * 4 + AS_HALFS * 2);
    float* shift_s = scale_s + 128;
    float* b2s = shift_s + 128;

    int tid = threadIdx.x, lane = tid & 31, wid = tid >> 5;
    int node0 = blockIdx.x << 7;   // 128 nodes per block

    copy_W_async(g_w1h, WsA, tid);
    CP_COMMIT();
    if (tid < 128) {
        float sc = gamma[tid] * rsqrtf(rvar[tid] + 1e-5f);
        scale_s[tid] = sc;
        shift_s[tid] = (b1[tid] - rmean[tid]) * sc + beta[tid];
        b2s[tid] = b2[tid];
    }
    // load 128 aggr rows (fp16) coalesced
    for (int i = tid; i < 4096; i += 512) {
        int n = i >> 5, q = i & 31;
        int node = node0 + n;
        if (node > N_NODES - 1) node = N_NODES - 1;
        uint2 h = __ldg((const uint2*)(g_aggrh + (size_t)node * 128) + q);
        *(uint2*)(As + n * 136 + q * 4) = h;
    }
    CP_WAIT0();
    __syncthreads();

    int wm = wid & 3, wn = wid >> 2;   // 4 m-tiles (32 rows) x 4 n-groups (32 cols)
    int rbase = wm * 32 + (lane >> 2);
    float C[8][4];

    // prefetch W2 while phase-1 mma runs
    copy_W_async(g_w2h, WsB, tid);
    CP_COMMIT();

    // ---- phase 1: h1 = relu(BN(A @ W1)) ----
    mma_phase(As, WsA, wm, wn, lane, C);
    __syncthreads();
#pragma unroll
    for (int mi = 0; mi < 2; mi++) {
#pragma unroll
        for (int nt = 0; nt < 4; nt++) {
            int c0 = wn * 32 + nt * 8 + (lane & 3) * 2;
            int rr = rbase + mi * 16;
            float* f = C[mi * 4 + nt];
            float sc0 = scale_s[c0], sc1 = scale_s[c0 + 1];
            float sh0 = shift_s[c0], sh1 = shift_s[c0 + 1];
            *(__half2*)(As + rr * 136 + c0) = __floats2half2_rn(
                fmaxf(f[0] * sc0 + sh0, 0.f), fmaxf(f[1] * sc1 + sh1, 0.f));
            *(__half2*)(As + (rr + 8) * 136 + c0) = __floats2half2_rn(
                fmaxf(f[2] * sc0 + sh0, 0.f), fmaxf(f[3] * sc1 + sh1, 0.f));
        }
    }
    CP_WAIT0();
    __syncthreads();

    // prefetch W3 (into WsA — all phase-1 reads of WsA finished at last barrier)
    copy_W_async(g_wch, WsA, tid);
    CP_COMMIT();

    // ---- phase 2: h2 = relu(A @ W2 + b2) ----
    mma_phase(As, WsB, wm, wn, lane, C);
    __syncthreads();
#pragma unroll
    for (int mi = 0; mi < 2; mi++) {
#pragma unroll
        for (int nt = 0; nt < 4; nt++) {
            int c0 = wn * 32 + nt * 8 + (lane & 3) * 2;
            int rr = rbase + mi * 16;
            float* f = C[mi * 4 + nt];
            float bb0 = b2s[c0], bb1 = b2s[c0 + 1];
            *(__half2*)(As + rr * 136 + c0) = __floats2half2_rn(
                fmaxf(f[0] + bb0, 0.f), fmaxf(f[1] + bb1, 0.f));
            *(__half2*)(As + (rr + 8) * 136 + c0) = __floats2half2_rn(
                fmaxf(f[2] + bb0, 0.f), fmaxf(f[3] + bb1, 0.f));
        }
    }
    CP_WAIT0();
    __syncthreads();

    // ---- phase 3: xw = A @ [Wmu|Wls]; xwh = half(dinv*xw) ----
    mma_phase(As, WsA, wm, wn, lane, C);
#pragma unroll
    for (int mi = 0; mi < 2; mi++) {
        int rr = rbase + mi * 16;
        int nodeA = node0 + rr;
        int nodeB = nodeA + 8;
        bool okA = nodeA < N_NODES, okB = nodeB < N_NODES;
        float dnA = okA ? g_dinv[nodeA] : 0.f;
        float dnB = okB ? g_dinv[nodeB] : 0.f;
#pragma unroll
        for (int nt = 0; nt < 4; nt++) {
            int c0 = wn * 32 + nt * 8 + (lane & 3) * 2;
            float* f = C[mi * 4 + nt];
            if (okA)
                *(__half2*)(g_xwh + (size_t)nodeA * 128 + c0) =
                    __floats2half2_rn(dnA * f[0], dnA * f[1]);
            if (okB)
                *(__half2*)(g_xwh + (size_t)nodeB * 128 + c0) =
                    __floats2half2_rn(dnB * f[2], dnB * f[3]);
        }
    }
}

// -------- GCN gather: out[n] = dinv[n]*(sum xwh[csr] + xwh[n]) + bias ------
__global__ __launch_bounds__(256) void k_gcn_gather(const float* __restrict__ bmu,
                                                    const float* __restrict__ bls,
                                                    float* __restrict__ out) {
    int n = blockIdx.x * 8 + (threadIdx.x >> 5);
    if (n >= N_NODES) return;
    int lane = threadIdx.x & 31;
    int beg = __ldg(g_off + n), end = __ldg(g_off + n + 1);
    const uint2* xh = (const uint2*)g_xwh;
    uint2 sh = __ldg(xh + (size_t)n * 32 + lane);  // self-loop term (dinv*xw)
    float2 accA = __half22float2(*(__half2*)&sh.x);
    float2 accB = __half22float2(*(__half2*)&sh.y);
    int j = beg;
    for (; j + 8 <= end; j += 8) {
        int idx[8];
#pragma unroll
        for (int t = 0; t < 8; t++) idx[t] = __ldg(g_csr + j + t);
        uint2 v[8];
#pragma unroll
        for (int t = 0; t < 8; t++) v[t] = __ldg(xh + (size_t)idx[t] * 32 + lane);
#pragma unroll
        for (int t = 0; t < 8; t++) {
            float2 f0 = __half22float2(*(__half2*)&v[t].x);
            float2 f1 = __half22float2(*(__half2*)&v[t].y);
            accA.x += f0.x; accA.y += f0.y;
            accB.x += f1.x; accB.y += f1.y;
        }
    }
    for (; j < end; j++) {
        int s = __ldg(g_csr + j);
        uint2 v = __ldg(xh + (size_t)s * 32 + lane);
        float2 f0 = __half22float2(*(__half2*)&v.x);
        float2 f1 = __half22float2(*(__half2*)&v.y);
        accA.x += f0.x; accA.y += f0.y;
        accB.x += f1.x; accB.y += f1.y;
    }
    float dn = g_dinv[n];
    int c0 = lane * 4;
    float4 bias = (c0 < 64) ? __ldg((const float4*)(bmu + c0))
                            : __ldg((const float4*)(bls + (c0 - 64)));
    float4 ov;
    ov.x = dn * accA.x + bias.x;
    ov.y = dn * accA.y + bias.y;
    ov.z = dn * accB.x + bias.z;
    ov.w = dn * accB.y + bias.w;
    float* ob = (c0 < 64) ? (out + (size_t)n * 64 + c0)
                          : (out + (size_t)N_NODES * 64 + (size_t)n * 64 + (c0 - 64));
    *(float4*)ob = ov;
}

extern "C" void kernel_launch(void* const* d_in, const int* in_sizes, int n_in,
                              void* d_out, int out_size) {
    const float* x     = (const float*)d_in[0];
    const void*  ei    = (const void*)d_in[1];
    const float* W1    = (const float*)d_in[2];
    const float* b1    = (const float*)d_in[3];
    const float* gamma = (const float*)d_in[4];
    const float* beta  = (const float*)d_in[5];
    const float* rmean = (const float*)d_in[6];
    const float* rvar  = (const float*)d_in[7];
    const float* W2    = (const float*)d_in[8];
    const float* b2    = (const float*)d_in[9];
    const float* Wmu   = (const float*)d_in[10];
    const float* bmu   = (const float*)d_in[11];
    const float* Wls   = (const float*)d_in[12];
    const float* bls   = (const float*)d_in[13];
    float* out = (float*)d_out;

    int E = in_sizes[1] / 2;

    const int SMEM = WS_HALFS * 2 * 2 + AS_HALFS * 2 + 384 * 4;  // 105984 B
    cudaFuncSetAttribute(k_mlp_hmma, cudaFuncAttributeMaxDynamicSharedMemorySize, SMEM);

    int cb = (E + 1023) / 1024;
    int eb = (E + 255) / 256;
    int nb = (N_NODES + 7) / 8;
    int mb = (N_NODES + 127) / 128;

    k_count_scan<<<cb, 1024>>>(ei, x, W1, W2, Wmu, Wls, E);            // 0
    k_fill<<<eb, 256>>>(ei, E);                                        // 1
    k_gin_gather<<<nb, 256>>>();                                       // 2
    k_mlp_hmma<<<mb, 512, SMEM>>>(b1, gamma, beta, rmean, rvar, b2);   // 3 <- profiled
    k_gcn_gather<<<nb, 256>>>(bmu, bls, out);                          // 4
}

// round 16
// speedup vs baseline: 4.4679x; 1.0571x over previous
#include <cuda_runtime.h>
#include <cuda_fp16.h>
#include <cstdint>

#define N_NODES 100000
#define DIMH 128
#define E_CAP 4000000
#define WS_HALFS (128 * 136)
#define AS_HALFS (128 * 136)

// -------- scratch (device globals; no allocation allowed) --------
__device__ __align__(16) __half g_xh[(size_t)N_NODES * DIMH];    // fp16 copy of x
__device__ __align__(16) __half g_aggrh[(size_t)N_NODES * DIMH]; // fp16 x+sum(neigh)
__device__ __align__(16) __half g_xwh[(size_t)N_NODES * DIMH];   // fp16 dinv-scaled xw
__device__ __align__(16) __half g_w1h[WS_HALFS];  // pre-swizzled fp16 W1
__device__ __align__(16) __half g_w2h[WS_HALFS];  // pre-swizzled fp16 W2
__device__ __align__(16) __half g_wch[WS_HALFS];  // pre-swizzled fp16 [Wmu|Wls]
__device__ float g_dinv[N_NODES];
__device__ __align__(16) int g_deg[N_NODES];  // zero at load; scan re-zeros each call
__device__ __align__(16) int g_off[N_NODES + 4];
__device__ __align__(16) int g_cur[N_NODES];
__device__ int   g_csr[E_CAP];
__device__ int   g_done;           // ticket for last-block scan; reset each call

// ==== count + conversions + (last block) scan, all in one launch ====
__global__ __launch_bounds__(1024) void k_count_scan(const void* __restrict__ ei,
                                                     const float* __restrict__ x,
                                                     const float* __restrict__ W1,
                                                     const float* __restrict__ W2,
                                                     const float* __restrict__ Wmu,
                                                     const float* __restrict__ Wls,
                                                     int E) {
    __shared__ int s_is64;
    __shared__ int s_last;
    if (threadIdx.x < 32) {
        unsigned w = __ldg((const unsigned*)ei + threadIdx.x * 2 + 1);
        unsigned b = __ballot_sync(0xffffffffu, w != 0u);
        if (threadIdx.x == 0) s_is64 = (b == 0u);
    }
    __syncthreads();
    int gid = blockIdx.x * 1024 + threadIdx.x;
    int total = gridDim.x * 1024;
    if (gid < E) {
        int d;
        if (s_is64) d = (int)__ldg((const long long*)ei + E + gid);
        else        d = __ldg((const int*)ei + E + gid);
        atomicAdd(&g_deg[d], 1);
    }
    // x (fp32) -> g_xh (fp16), float4 granularity
    const float4* x4 = (const float4*)x;
    uint2* xh4 = (uint2*)g_xh;
    const int NH4 = N_NODES * (DIMH / 4);
    for (int i = gid; i < NH4; i += total) {
        float4 v = __ldg(x4 + i);
        uint2 h;
        *(__half2*)&h.x = __floats2half2_rn(v.x, v.y);
        *(__half2*)&h.y = __floats2half2_rn(v.z, v.w);
        xh4[i] = h;
    }
    // weights -> fp16 smem-image layout (row k at k*136, float4 chunk c4 at c4*4)
    for (int i = gid; i < 3 * 4096; i += total) {
        int w = i >> 12, j = i & 4095;
        int k = j >> 5, c4 = j & 31;
        float4 v;
        __half* dst;
        if (w == 0)      { v = __ldg((const float4*)W1 + j); dst = g_w1h; }
        else if (w == 1) { v = __ldg((const float4*)W2 + j); dst = g_w2h; }
        else {
            v = (c4 < 16) ? __ldg((const float4*)Wmu + k * 16 + c4)
                          : __ldg((const float4*)Wls + k * 16 + (c4 - 16));
            dst = g_wch;
        }
        uint2 h;
        *(__half2*)&h.x = __floats2half2_rn(v.x, v.y);
        *(__half2*)&h.y = __floats2half2_rn(v.z, v.w);
        *(uint2*)(dst + k * 136 + c4 * 4) = h;
    }

    // ---- ticket: last block to finish runs the scan ----
    __threadfence();
    __syncthreads();
    if (threadIdx.x == 0)
        s_last = (atomicAdd(&g_done, 1) == (int)gridDim.x - 1);
    __syncthreads();
    if (!s_last) return;
    if (threadIdx.x == 0) g_done = 0;  // reset for next graph replay

    // ---- vectorized scan: 4 ints/thread/tile (25 tiles) ----
    __shared__ int wsum[32];
    __shared__ int s_carry;
    int tid = threadIdx.x, lane = tid & 31, wid = tid >> 5;
    if (tid == 0) s_carry = 0;
    __syncthreads();
    const int TILE = 4096;
    const int NT = (N_NODES + TILE - 1) / TILE;  // 25
    for (int t = 0; t < NT; t++) {
        int base = t * TILE + tid * 4;
        int4 d4 = make_int4(0, 0, 0, 0);
        if (base < N_NODES) d4 = *(const int4*)(g_deg + base);  // N%4==0 -> safe
        int tot = d4.x + d4.y + d4.z + d4.w;
        int v = tot;
#pragma unroll
        for (int o = 1; o < 32; o <<= 1) {
            int u = __shfl_up_sync(~0u, v, o);
            if (lane >= o) v += u;
        }
        if (lane == 31) wsum[wid] = v;
        __syncthreads();
        if (wid == 0) {
            int w = wsum[lane];
#pragma unroll
            for (int o = 1; o < 32; o <<= 1) {
                int u = __shfl_up_sync(~0u, w, o);
                if (lane >= o) w += u;
            }
            wsum[lane] = w;
        }
        __syncthreads();
        int excl = v - tot + ((wid > 0) ? wsum[wid - 1] : 0) + s_carry;
        if (base < N_NODES) {
            int4 off4, cur4;
            off4.x = excl;
            off4.y = excl + d4.x;
            off4.z = excl + d4.x + d4.y;
            off4.w = excl + d4.x + d4.y + d4.z;
            cur4 = off4;
            *(int4*)(g_off + base) = off4;
            *(int4*)(g_cur + base) = cur4;
            float4 di4;
            di4.x = rsqrtf((float)d4.x + 1.0f);
            di4.y = rsqrtf((float)d4.y + 1.0f);
            di4.z = rsqrtf((float)d4.z + 1.0f);
            di4.w = rsqrtf((float)d4.w + 1.0f);
            *(float4*)(g_dinv + base) = di4;
            *(int4*)(g_deg + base) = make_int4(0, 0, 0, 0);  // reset for next call
        }
        __syncthreads();
        if (tid == 0) s_carry += wsum[31];
        __syncthreads();
    }
    if (tid == 0) g_off[N_NODES] = s_carry;
}

// -------- fill CSR (reads ei directly) --------
__global__ __launch_bounds__(256) void k_fill(const void* __restrict__ ei, int E) {
    __shared__ int s_is64;
    if (threadIdx.x < 32) {
        unsigned w = __ldg((const unsigned*)ei + threadIdx.x * 2 + 1);
        unsigned b = __ballot_sync(0xffffffffu, w != 0u);
        if (threadIdx.x == 0) s_is64 = (b == 0u);
    }
    __syncthreads();
    int e = blockIdx.x * 256 + threadIdx.x;
    if (e >= E) return;
    int s, d;
    if (s_is64) {
        s = (int)__ldg((const long long*)ei + e);
        d = (int)__ldg((const long long*)ei + E + e);
    } else {
        s = __ldg((const int*)ei + e);
        d = __ldg((const int*)ei + E + e);
    }
    int pos = atomicAdd(&g_cur[d], 1);
    g_csr[pos] = s;
}

// -------- GIN gather (fp16): aggrh[n] = half(xh[n] + sum xh[csr]) ----------
__global__ __launch_bounds__(256) void k_gin_gather() {
    int n = blockIdx.x * 8 + (threadIdx.x >> 5);
    if (n >= N_NODES) return;
    int lane = threadIdx.x & 31;
    int beg = __ldg(g_off + n), end = __ldg(g_off + n + 1);
    const uint2* xh = (const uint2*)g_xh;
    uint2 sh = __ldg(xh + (size_t)n * 32 + lane);  // self term (fp16)
    float2 accA = __half22float2(*(__half2*)&sh.x);
    float2 accB = __half22float2(*(__half2*)&sh.y);
    int j = beg;
    for (; j + 8 <= end; j += 8) {
        int idx[8];
#pragma unroll
        for (int t = 0; t < 8; t++) idx[t] = __ldg(g_csr + j + t);
        uint2 v[8];
#pragma unroll
        for (int t = 0; t < 8; t++) v[t] = __ldg(xh + (size_t)idx[t] * 32 + lane);
#pragma unroll
        for (int t = 0; t < 8; t++) {
            float2 f0 = __half22float2(*(__half2*)&v[t].x);
            float2 f1 = __half22float2(*(__half2*)&v[t].y);
            accA.x += f0.x; accA.y += f0.y;
            accB.x += f1.x; accB.y += f1.y;
        }
    }
    for (; j < end; j++) {
        int s = __ldg(g_csr + j);
        uint2 v = __ldg(xh + (size_t)s * 32 + lane);
        float2 f0 = __half22float2(*(__half2*)&v.x);
        float2 f1 = __half22float2(*(__half2*)&v.y);
        accA.x += f0.x; accA.y += f0.y;
        accB.x += f1.x; accB.y += f1.y;
    }
    uint2 hx;
    *(__half2*)&hx.x = __floats2half2_rn(accA.x, accA.y);
    *(__half2*)&hx.y = __floats2half2_rn(accB.x, accB.y);
    *(uint2*)(g_aggrh + (size_t)n * 128 + lane * 4) = hx;
}

// ===================== HMMA plumbing =====================
__device__ __forceinline__ uint32_t smem_u32(const void* p) {
    return (uint32_t)__cvta_generic_to_shared(p);
}
__device__ __forceinline__ void ldmat_x4(uint32_t addr, uint32_t& r0, uint32_t& r1,
                                         uint32_t& r2, uint32_t& r3) {
    asm volatile("ldmatrix.sync.aligned.m8n8.x4.shared.b16 {%0,%1,%2,%3}, [%4];"
                 : "=r"(r0), "=r"(r1), "=r"(r2), "=r"(r3) : "r"(addr));
}
__device__ __forceinline__ void ldmat_x4_t(uint32_t addr, uint32_t& r0, uint32_t& r1,
                                           uint32_t& r2, uint32_t& r3) {
    asm volatile("ldmatrix.sync.aligned.m8n8.x4.trans.shared.b16 {%0,%1,%2,%3}, [%4];"
                 : "=r"(r0), "=r"(r1), "=r"(r2), "=r"(r3) : "r"(addr));
}
__device__ __forceinline__ void mma16816(float* c, uint32_t a0, uint32_t a1, uint32_t a2,
                                         uint32_t a3, uint32_t b0, uint32_t b1) {
    asm volatile(
        "mma.sync.aligned.m16n8k16.row.col.f32.f16.f16.f32 "
        "{%0,%1,%2,%3}, {%4,%5,%6,%7}, {%8,%9}, {%0,%1,%2,%3};"
        : "+f"(c[0]), "+f"(c[1]), "+f"(c[2]), "+f"(c[3])
        : "r"(a0), "r"(a1), "r"(a2), "r"(a3), "r"(b0), "r"(b1));
}

// one GEMM phase, 4x4 warp tile: warp owns rows wm*32..+31, cols wn*32..+31
__device__ __forceinline__ void mma_phase(const __half* As, const __half* Ws,
                                          int wm, int wn, int lane, float C[8][4]) {
#pragma unroll
    for (int t = 0; t < 8; t++) {
        C[t][0] = 0.f; C[t][1] = 0.f; C[t][2] = 0.f; C[t][3] = 0.f;
    }
    int l15 = lane & 15, l16 = lane >> 4;
    const __half* a0 = As + (wm * 32 + l15) * 136 + l16 * 8;
    const __half* a1 = a0 + 16 * 136;
    const __half* bb = Ws + l15 * 136 + wn * 32 + l16 * 8;
#pragma unroll
    for (int k = 0; k < 8; k++) {
        uint32_t A0[4], A1[4];
        ldmat_x4(smem_u32(a0 + k * 16), A0[0], A0[1], A0[2], A0[3]);
        ldmat_x4(smem_u32(a1 + k * 16), A1[0], A1[1], A1[2], A1[3]);
        uint32_t b0, b1, b2, b3, b4, b5, b6, b7;
        ldmat_x4_t(smem_u32(bb + (k * 16) * 136), b0, b1, b2, b3);
        ldmat_x4_t(smem_u32(bb + (k * 16) * 136 + 16), b4, b5, b6, b7);
        mma16816(C[0], A0[0], A0[1], A0[2], A0[3], b0, b1);
        mma16816(C[1], A0[0], A0[1], A0[2], A0[3], b2, b3);
        mma16816(C[2], A0[0], A0[1], A0[2], A0[3], b4, b5);
        mma16816(C[3], A0[0], A0[1], A0[2], A0[3], b6, b7);
        mma16816(C[4], A1[0], A1[1], A1[2], A1[3], b0, b1);
        mma16816(C[5], A1[0], A1[1], A1[2], A1[3], b2, b3);
        mma16816(C[6], A1[0], A1[1], A1[2], A1[3], b4, b5);
        mma16816(C[7], A1[0], A1[1], A1[2], A1[3], b6, b7);
    }
}

// -------- cp.async helpers --------
__device__ __forceinline__ void cpasync16(uint32_t saddr, const void* g) {
    asm volatile("cp.async.cg.shared.global [%0], [%1], 16;" :: "r"(saddr), "l"(g));
}
#define CP_COMMIT() asm volatile("cp.async.commit_group;" ::: "memory")
#define CP_WAIT0()  asm volatile("cp.async.wait_group 0;" ::: "memory")

// async copy pre-swizzled fp16 W image into smem — FULL 34816 B (2176 chunks)
__device__ __forceinline__ void copy_W_async(const __half* __restrict__ src,
                                             __half* __restrict__ Ws, int tid) {
    const char* s = (const char*)src;
    char* d = (char*)Ws;
    for (int i = tid; i < WS_HALFS / 8; i += 512) {
        cpasync16(smem_u32(d + i * 16), s + i * 16);
    }
}

// ===================== 3-layer HMMA GEMM: 128 nodes/block, 512 threads ======
__global__ __launch_bounds__(512, 2) void k_mlp_hmma(const float* __restrict__ b1,
                                                     const float* __restrict__ gamma,
                                                     const float* __restrict__ beta,
                                                     const float* __restrict__ rmean,
                                                     const float* __restrict__ rvar,
                                                     const float* __restrict__ b2) {
    extern __shared__ char smraw[];
    __half* WsA = (__half*)smraw;                            // 34816 B
    __half* WsB = (__half*)(smraw + WS_HALFS * 2);           // 34816 B
    __half* As  = (__half*)(smraw + WS_HALFS * 4);           // 34816 B
    float* scale_s = (float*)(smraw + WS_HALFS * 4 + AS_HALFS * 2);
    float* shift_s = scale_s + 128;
    float* b2s = shift_s + 128;

    int tid = threadIdx.x, lane = tid & 31, wid = tid >> 5;
    int node0 = blockIdx.x << 7;   // 128 nodes per block

    copy_W_async(g_w1h, WsA, tid);
    CP_COMMIT();
    if (tid < 128) {
        float sc = gamma[tid] * rsqrtf(rvar[tid] + 1e-5f);
        scale_s[tid] = sc;
        shift_s[tid] = (b1[tid] - rmean[tid]) * sc + beta[tid];
        b2s[tid] = b2[tid];
    }
    // load 128 aggr rows (fp16) coalesced
    for (int i = tid; i < 4096; i += 512) {
        int n = i >> 5, q = i & 31;
        int node = node0 + n;
        if (node > N_NODES - 1) node = N_NODES - 1;
        uint2 h = __ldg((const uint2*)(g_aggrh + (size_t)node * 128) + q);
        *(uint2*)(As + n * 136 + q * 4) = h;
    }
    CP_WAIT0();
    __syncthreads();

    int wm = wid & 3, wn = wid >> 2;   // 4 m-tiles (32 rows) x 4 n-groups (32 cols)
    int rbase = wm * 32 + (lane >> 2);
    float C[8][4];

    // prefetch W2 while phase-1 mma runs
    copy_W_async(g_w2h, WsB, tid);
    CP_COMMIT();

    // ---- phase 1: h1 = relu(BN(A @ W1)) ----
    mma_phase(As, WsA, wm, wn, lane, C);
    __syncthreads();
#pragma unroll
    for (int mi = 0; mi < 2; mi++) {
#pragma unroll
        for (int nt = 0; nt < 4; nt++) {
            int c0 = wn * 32 + nt * 8 + (lane & 3) * 2;
            int rr = rbase + mi * 16;
            float* f = C[mi * 4 + nt];
            float sc0 = scale_s[c0], sc1 = scale_s[c0 + 1];
            float sh0 = shift_s[c0], sh1 = shift_s[c0 + 1];
            *(__half2*)(As + rr * 136 + c0) = __floats2half2_rn(
                fmaxf(f[0] * sc0 + sh0, 0.f), fmaxf(f[1] * sc1 + sh1, 0.f));
            *(__half2*)(As + (rr + 8) * 136 + c0) = __floats2half2_rn(
                fmaxf(f[2] * sc0 + sh0, 0.f), fmaxf(f[3] * sc1 + sh1, 0.f));
        }
    }
    CP_WAIT0();
    __syncthreads();

    // prefetch W3 (into WsA — all phase-1 reads of WsA finished at last barrier)
    copy_W_async(g_wch, WsA, tid);
    CP_COMMIT();

    // ---- phase 2: h2 = relu(A @ W2 + b2) ----
    mma_phase(As, WsB, wm, wn, lane, C);
    __syncthreads();
#pragma unroll
    for (int mi = 0; mi < 2; mi++) {
#pragma unroll
        for (int nt = 0; nt < 4; nt++) {
            int c0 = wn * 32 + nt * 8 + (lane & 3) * 2;
            int rr = rbase + mi * 16;
            float* f = C[mi * 4 + nt];
            float bb0 = b2s[c0], bb1 = b2s[c0 + 1];
            *(__half2*)(As + rr * 136 + c0) = __floats2half2_rn(
                fmaxf(f[0] + bb0, 0.f), fmaxf(f[1] + bb1, 0.f));
            *(__half2*)(As + (rr + 8) * 136 + c0) = __floats2half2_rn(
                fmaxf(f[2] + bb0, 0.f), fmaxf(f[3] + bb1, 0.f));
        }
    }
    CP_WAIT0();
    __syncthreads();

    // ---- phase 3: xw = A @ [Wmu|Wls]; xwh = half(dinv*xw) ----
    mma_phase(As, WsA, wm, wn, lane, C);
#pragma unroll
    for (int mi = 0; mi < 2; mi++) {
        int rr = rbase + mi * 16;
        int nodeA = node0 + rr;
        int nodeB = nodeA + 8;
        bool okA = nodeA < N_NODES, okB = nodeB < N_NODES;
        float dnA = okA ? g_dinv[nodeA] : 0.f;
        float dnB = okB ? g_dinv[nodeB] : 0.f;
#pragma unroll
        for (int nt = 0; nt < 4; nt++) {
            int c0 = wn * 32 + nt * 8 + (lane & 3) * 2;
            float* f = C[mi * 4 + nt];
            if (okA)
                *(__half2*)(g_xwh + (size_t)nodeA * 128 + c0) =
                    __floats2half2_rn(dnA * f[0], dnA * f[1]);
            if (okB)
                *(__half2*)(g_xwh + (size_t)nodeB * 128 + c0) =
                    __floats2half2_rn(dnB * f[2], dnB * f[3]);
        }
    }
}

// -------- GCN gather: out[n] = dinv[n]*(sum xwh[csr] + xwh[n]) + bias ------
__global__ __launch_bounds__(256) void k_gcn_gather(const float* __restrict__ bmu,
                                                    const float* __restrict__ bls,
                                                    float* __restrict__ out) {
    int n = blockIdx.x * 8 + (threadIdx.x >> 5);
    if (n >= N_NODES) return;
    int lane = threadIdx.x & 31;
    int beg = __ldg(g_off + n), end = __ldg(g_off + n + 1);
    const uint2* xh = (const uint2*)g_xwh;
    uint2 sh = __ldg(xh + (size_t)n * 32 + lane);  // self-loop term (dinv*xw)
    float2 accA = __half22float2(*(__half2*)&sh.x);
    float2 accB = __half22float2(*(__half2*)&sh.y);
    int j = beg;
    for (; j + 8 <= end; j += 8) {
        int idx[8];
#pragma unroll
        for (int t = 0; t < 8; t++) idx[t] = __ldg(g_csr + j + t);
        uint2 v[8];
#pragma unroll
        for (int t = 0; t < 8; t++) v[t] = __ldg(xh + (size_t)idx[t] * 32 + lane);
#pragma unroll
        for (int t = 0; t < 8; t++) {
            float2 f0 = __half22float2(*(__half2*)&v[t].x);
            float2 f1 = __half22float2(*(__half2*)&v[t].y);
            accA.x += f0.x; accA.y += f0.y;
            accB.x += f1.x; accB.y += f1.y;
        }
    }
    for (; j < end; j++) {
        int s = __ldg(g_csr + j);
        uint2 v = __ldg(xh + (size_t)s * 32 + lane);
        float2 f0 = __half22float2(*(__half2*)&v.x);
        float2 f1 = __half22float2(*(__half2*)&v.y);
        accA.x += f0.x; accA.y += f0.y;
        accB.x += f1.x; accB.y += f1.y;
    }
    float dn = g_dinv[n];
    int c0 = lane * 4;
    float4 bias = (c0 < 64) ? __ldg((const float4*)(bmu + c0))
                            : __ldg((const float4*)(bls + (c0 - 64)));
    float4 ov;
    ov.x = dn * accA.x + bias.x;
    ov.y = dn * accA.y + bias.y;
    ov.z = dn * accB.x + bias.z;
    ov.w = dn * accB.y + bias.w;
    float* ob = (c0 < 64) ? (out + (size_t)n * 64 + c0)
                          : (out + (size_t)N_NODES * 64 + (size_t)n * 64 + (c0 - 64));
    *(float4*)ob = ov;
}

extern "C" void kernel_launch(void* const* d_in, const int* in_sizes, int n_in,
                              void* d_out, int out_size) {
    const float* x     = (const float*)d_in[0];
    const void*  ei    = (const void*)d_in[1];
    const float* W1    = (const float*)d_in[2];
    const float* b1    = (const float*)d_in[3];
    const float* gamma = (const float*)d_in[4];
    const float* beta  = (const float*)d_in[5];
    const float* rmean = (const float*)d_in[6];
    const float* rvar  = (const float*)d_in[7];
    const float* W2    = (const float*)d_in[8];
    const float* b2    = (const float*)d_in[9];
    const float* Wmu   = (const float*)d_in[10];
    const float* bmu   = (const float*)d_in[11];
    const float* Wls   = (const float*)d_in[12];
    const float* bls   = (const float*)d_in[13];
    float* out = (float*)d_out;

    int E = in_sizes[1] / 2;

    const int SMEM = WS_HALFS * 2 * 2 + AS_HALFS * 2 + 384 * 4;  // 105984 B
    cudaFuncSetAttribute(k_mlp_hmma, cudaFuncAttributeMaxDynamicSharedMemorySize, SMEM);

    int cb = (E + 1023) / 1024;
    int eb = (E + 255) / 256;
    int nb = (N_NODES + 7) / 8;
    int mb = (N_NODES + 127) / 128;

    k_count_scan<<<cb, 1024>>>(ei, x, W1, W2, Wmu, Wls, E);            // 0
    k_fill<<<eb, 256>>>(ei, E);                                        // 1
    k_gin_gather<<<nb, 256>>>();                                       // 2
    k_mlp_hmma<<<mb, 512, SMEM>>>(b1, gamma, beta, rmean, rvar, b2);   // 3 <- profiled
    k_gcn_gather<<<nb, 256>>>(bmu, bls, out);                          // 4
}